// round 5
// baseline (speedup 1.0000x reference)
#include <cuda_runtime.h>
#include <cuda_bf16.h>
#include <math.h>
#include <stdint.h>

// Problem constants
#define D      512
#define NNODES 20000
#define NEDGES 100000
#define EPRIME (NEDGES + NNODES)
#define H1v    8
#define C1v    64
#define H2v    4
#define C2v    128
#define CHUNK  256

// ---------------- scratch (device globals; no allocation allowed) -------------
__device__ float g_xp[(size_t)NNODES * D];      // xp1, then reused as xp2
__device__ float g_h[(size_t)NNODES * D];       // hidden after layer 1
__device__ float g_asrc[(size_t)NNODES * H1v];
__device__ float g_adst[(size_t)NNODES * H1v];
__device__ float g_e[(size_t)EPRIME * H1v];     // edge scores (reused layer 2)
__device__ float g_logits[(size_t)NNODES * C2v];
__device__ int   g_deg[NNODES];
__device__ int   g_rowstart[NNODES];
__device__ int   g_cursor[NNODES];
__device__ int   g_csr[EPRIME];
__device__ float g_accum[2];
__device__ int   g_mask_byte;
__device__ int   g_total;
// bf16 hi/lo split buffers for tensor-core GEMM
__device__ __nv_bfloat16 g_Ahi[(size_t)NNODES * D];
__device__ __nv_bfloat16 g_Alo[(size_t)NNODES * D];
__device__ __nv_bfloat16 g_Bhi[(size_t)D * D];
__device__ __nv_bfloat16 g_Blo[(size_t)D * D];

// ---------------- helpers ----------------------------------------------------
__device__ __forceinline__ float warp_max(float v) {
    #pragma unroll
    for (int o = 16; o; o >>= 1) v = fmaxf(v, __shfl_xor_sync(0xffffffffu, v, o));
    return v;
}
__device__ __forceinline__ float warp_sum(float v) {
    #pragma unroll
    for (int o = 16; o; o >>= 1) v += __shfl_xor_sync(0xffffffffu, v, o);
    return v;
}

__device__ __forceinline__ void mma16816(float* c, const uint32_t* a, const uint32_t* b) {
    asm volatile(
        "mma.sync.aligned.m16n8k16.row.col.f32.bf16.bf16.f32 "
        "{%0,%1,%2,%3}, {%4,%5,%6,%7}, {%8,%9}, {%0,%1,%2,%3};\n"
        : "+f"(c[0]), "+f"(c[1]), "+f"(c[2]), "+f"(c[3])
        : "r"(a[0]), "r"(a[1]), "r"(a[2]), "r"(a[3]), "r"(b[0]), "r"(b[1]));
}
__device__ __forceinline__ void ldsm4(uint32_t* r, uint32_t addr) {
    asm volatile("ldmatrix.sync.aligned.m8n8.x4.shared.b16 {%0,%1,%2,%3}, [%4];\n"
        : "=r"(r[0]), "=r"(r[1]), "=r"(r[2]), "=r"(r[3]) : "r"(addr));
}
__device__ __forceinline__ void ldsm4t(uint32_t* r, uint32_t addr) {
    asm volatile("ldmatrix.sync.aligned.m8n8.x4.trans.shared.b16 {%0,%1,%2,%3}, [%4];\n"
        : "=r"(r[0]), "=r"(r[1]), "=r"(r[2]), "=r"(r[3]) : "r"(addr));
}
__device__ __forceinline__ void cpasync16(uint32_t dst, const void* src, int srcsize) {
    asm volatile("cp.async.cg.shared.global [%0], [%1], 16, %2;\n"
        :: "r"(dst), "l"(src), "r"(srcsize));
}
__device__ __forceinline__ void cp_commit() {
    asm volatile("cp.async.commit_group;\n");
}
template<int NW> __device__ __forceinline__ void cp_wait() {
    asm volatile("cp.async.wait_group %0;\n" :: "n"(NW));
}

// ---------------- init / CSR build -------------------------------------------
__global__ void init_kernel(int N) {
    int i = blockIdx.x * blockDim.x + threadIdx.x;
    if (i < N) g_deg[i] = 0;
    if (i == 0) { g_accum[0] = 0.f; g_accum[1] = 0.f; g_mask_byte = 0; g_total = 0; }
}

__global__ void detect_mask_kernel(const unsigned int* __restrict__ m, int nwords) {
    int i = blockIdx.x * blockDim.x + threadIdx.x;
    if (i < nwords) {
        unsigned v = m[i];
        if (v != 0u && v != 1u && v != 0x3F800000u) atomicOr(&g_mask_byte, 1);
    }
}

__global__ void hist_kernel(const int* __restrict__ ei, int E, int N) {
    int i = blockIdx.x * blockDim.x + threadIdx.x;
    if (i >= E + N) return;
    int d = (i < E) ? ei[E + i] : (i - E);
    atomicAdd(&g_deg[d], 1);
}

// Assign each node a contiguous segment (placement order is immaterial)
__global__ void offsets_kernel(int N) {
    int i = blockIdx.x * blockDim.x + threadIdx.x;
    if (i < N) {
        int base = atomicAdd(&g_total, g_deg[i]);
        g_rowstart[i] = base;
        g_cursor[i] = base;
    }
}

__global__ void scatter_kernel(const int* __restrict__ ei, int E, int N) {
    int i = blockIdx.x * blockDim.x + threadIdx.x;
    if (i >= E + N) return;
    int d = (i < E) ? ei[E + i] : (i - E);
    int pos = atomicAdd(&g_cursor[d], 1);
    g_csr[pos] = i;
}

// ---------------- bf16 hi/lo split --------------------------------------------
__global__ void split_kernel(const float* __restrict__ x,
                             __nv_bfloat16* __restrict__ hi,
                             __nv_bfloat16* __restrict__ lo, int n) {
    for (int i = blockIdx.x * blockDim.x + threadIdx.x; i < n; i += gridDim.x * blockDim.x) {
        float v = x[i];
        __nv_bfloat16 h = __float2bfloat16(v);
        hi[i] = h;
        lo[i] = __float2bfloat16(v - __bfloat162float(h));
    }
}

// ---------------- tensor-core GEMM: C[M,512] = A[M,512] @ B[512,512] -----------
// bf16 hi/lo split, 3 products into fp32 accumulators via mma.m16n8k16
#define LDA_S 40     // 32 + 8 pad (elems)
#define LDB_S 136    // 128 + 8 pad (elems)
#define A_HI_OFF 0
#define A_LO_OFF (128 * LDA_S * 2)                    // 10240
#define B_HI_OFF (A_LO_OFF * 2)                       // 20480
#define B_LO_OFF (B_HI_OFF + 32 * LDB_S * 2)          // 29184
#define STAGE_BYTES (B_LO_OFF + 32 * LDB_S * 2)       // 37888
#define GEMM_SMEM (2 * STAGE_BYTES)                   // 75776

extern __shared__ char smem_raw[];

__global__ __launch_bounds__(256, 1)
void gemm_mma_kernel(const __nv_bfloat16* __restrict__ Ahi,
                     const __nv_bfloat16* __restrict__ Alo,
                     const __nv_bfloat16* __restrict__ Bhi,
                     const __nv_bfloat16* __restrict__ Blo,
                     float* __restrict__ C, int M) {
    const int tid = threadIdx.x;
    const int lane = tid & 31;
    const int wid = tid >> 5;
    const int m0 = blockIdx.y * 128;
    const int n0 = blockIdx.x * 128;
    const int warp_m = wid >> 2;          // 0..1 -> 64 rows
    const int warp_n = wid & 3;           // 0..3 -> 32 cols
    const int m_base = warp_m * 64;
    const int n_base = warp_n * 32;

    uint32_t smem_u32 = (uint32_t)__cvta_generic_to_shared(smem_raw);

    // per-thread load slots
    const int arow0 = tid >> 2, acol0 = (tid & 3) * 8;         // + row 64 for second chunk
    const int brow0 = tid >> 4, bcol0 = (tid & 15) * 8;        // + row 16 for second chunk

    float acc[4][4][4];
    #pragma unroll
    for (int i = 0; i < 4; i++)
        #pragma unroll
        for (int j = 0; j < 4; j++)
            #pragma unroll
            for (int k = 0; k < 4; k++) acc[i][j][k] = 0.f;

    const int NIT = D / 32;   // 16

    auto load_stage = [&](int it, int s) {
        int k0 = it * 32;
        uint32_t base = smem_u32 + s * STAGE_BYTES;
        #pragma unroll
        for (int c = 0; c < 2; c++) {
            int row = arow0 + c * 64;
            int gr = m0 + row;
            int ok = (gr < M) ? 16 : 0;
            size_t goff = (size_t)gr * D + k0 + acol0;
            uint32_t soff = (uint32_t)(row * LDA_S + acol0) * 2;
            cpasync16(base + A_HI_OFF + soff, Ahi + goff, ok);
            cpasync16(base + A_LO_OFF + soff, Alo + goff, ok);
        }
        #pragma unroll
        for (int c = 0; c < 2; c++) {
            int row = brow0 + c * 16;
            size_t goff = (size_t)(k0 + row) * D + n0 + bcol0;
            uint32_t soff = (uint32_t)(row * LDB_S + bcol0) * 2;
            cpasync16(base + B_HI_OFF + soff, Bhi + goff, 16);
            cpasync16(base + B_LO_OFF + soff, Blo + goff, 16);
        }
    };

    load_stage(0, 0);
    cp_commit();

    for (int it = 0; it < NIT; it++) {
        if (it + 1 < NIT) {
            load_stage(it + 1, (it + 1) & 1);
            cp_commit();
            cp_wait<1>();
        } else {
            cp_wait<0>();
        }
        __syncthreads();

        uint32_t stg = smem_u32 + (it & 1) * STAGE_BYTES;
        #pragma unroll
        for (int kk = 0; kk < 2; kk++) {
            int kof = kk * 16;
            uint32_t ahi[4][4], alo[4][4];
            #pragma unroll
            for (int mt = 0; mt < 4; mt++) {
                uint32_t off = (uint32_t)((m_base + mt * 16 + (lane & 15)) * LDA_S
                                          + kof + 8 * (lane >> 4)) * 2;
                ldsm4(ahi[mt], stg + A_HI_OFF + off);
                ldsm4(alo[mt], stg + A_LO_OFF + off);
            }
            uint32_t bhi[4][2], blo[4][2];
            #pragma unroll
            for (int p = 0; p < 2; p++) {
                uint32_t off = (uint32_t)((kof + (lane & 7) + 8 * ((lane >> 3) & 1)) * LDB_S
                                          + n_base + p * 16 + 8 * (lane >> 4)) * 2;
                uint32_t r[4];
                ldsm4t(r, stg + B_HI_OFF + off);
                bhi[p * 2][0] = r[0]; bhi[p * 2][1] = r[1];
                bhi[p * 2 + 1][0] = r[2]; bhi[p * 2 + 1][1] = r[3];
                ldsm4t(r, stg + B_LO_OFF + off);
                blo[p * 2][0] = r[0]; blo[p * 2][1] = r[1];
                blo[p * 2 + 1][0] = r[2]; blo[p * 2 + 1][1] = r[3];
            }
            #pragma unroll
            for (int mt = 0; mt < 4; mt++)
                #pragma unroll
                for (int nt = 0; nt < 4; nt++) {
                    mma16816(acc[mt][nt], ahi[mt], bhi[nt]);
                    mma16816(acc[mt][nt], ahi[mt], blo[nt]);
                    mma16816(acc[mt][nt], alo[mt], bhi[nt]);
                }
        }
        __syncthreads();
    }

    // epilogue
    const int gid = lane >> 2, t4 = lane & 3;
    #pragma unroll
    for (int mt = 0; mt < 4; mt++) {
        int r0 = m0 + m_base + mt * 16 + gid;
        int r1 = r0 + 8;
        #pragma unroll
        for (int nt = 0; nt < 4; nt++) {
            int col = n0 + n_base + nt * 8 + t4 * 2;
            if (r0 < M) *(float2*)&C[(size_t)r0 * D + col] = make_float2(acc[mt][nt][0], acc[mt][nt][1]);
            if (r1 < M) *(float2*)&C[(size_t)r1 * D + col] = make_float2(acc[mt][nt][2], acc[mt][nt][3]);
        }
    }
}

// ---------------- per-node attention dot products ----------------------------
__global__ void att_kernel(const float* __restrict__ xp,
                           const float* __restrict__ a_src, const float* __restrict__ a_dst,
                           float* __restrict__ asrc, float* __restrict__ adst,
                           int N, int H, int C) {
    int warp = (blockIdx.x * blockDim.x + threadIdx.x) >> 5;
    int lane = threadIdx.x & 31;
    if (warp >= N) return;
    const float* row = xp + (size_t)warp * D;
    for (int h = 0; h < H; h++) {
        float ss = 0.f, sd = 0.f;
        for (int j = lane; j < C; j += 32) {
            float xv = row[h * C + j];
            ss += xv * a_src[h * C + j];
            sd += xv * a_dst[h * C + j];
        }
        ss = warp_sum(ss);
        sd = warp_sum(sd);
        if (lane == 0) { asrc[warp * H + h] = ss; adst[warp * H + h] = sd; }
    }
}

// ---------------- per-edge leaky-relu scores ---------------------------------
__global__ void score_kernel(const float* __restrict__ asrc, const float* __restrict__ adst,
                             const int* __restrict__ ei, int E, int N, int H) {
    int i = blockIdx.x * blockDim.x + threadIdx.x;
    if (i >= E + N) return;
    int s, d;
    if (i < E) { s = ei[i]; d = ei[E + i]; } else { s = d = i - E; }
    for (int h = 0; h < H; h++) {
        float v = asrc[s * H + h] + adst[d * H + h];
        g_e[(size_t)i * H + h] = v > 0.f ? v : 0.2f * v;
    }
}

// ---------------- per-dst softmax + aggregate (block per node) ---------------
__global__ __launch_bounds__(256)
void agg_kernel(const float* __restrict__ xp, const float* __restrict__ e,
                const float* __restrict__ bias, float* __restrict__ out,
                const int* __restrict__ ei, int E, int H, int C, int mode) {
    __shared__ float sh_alpha[CHUNK * H1v];
    __shared__ int   sh_src[CHUNK];
    __shared__ float sh_m[H1v], sh_s[H1v];
    __shared__ float sh_red[512];
    int n = blockIdx.x;
    int tid = threadIdx.x;
    int w = tid >> 5, lane = tid & 31;
    int beg = g_rowstart[n], end = beg + g_deg[n];

    if (w < H) {
        float m = -1e30f;
        for (int i = beg + lane; i < end; i += 32)
            m = fmaxf(m, e[(size_t)g_csr[i] * H + w]);
        m = warp_max(m);
        float s = 0.f;
        for (int i = beg + lane; i < end; i += 32)
            s += expf(e[(size_t)g_csr[i] * H + w] - m);
        s = warp_sum(s);
        if (lane == 0) { sh_m[w] = m; sh_s[w] = s + 1e-16f; }
    }
    __syncthreads();

    int h0 = tid / C, h1 = (tid + 256) / C;
    float acc0 = 0.f, acc1 = 0.f;
    for (int cs = beg; cs < end; cs += CHUNK) {
        int cn = min(CHUNK, end - cs);
        for (int idx = tid; idx < cn; idx += 256) {
            int eid = g_csr[cs + idx];
            sh_src[idx] = (eid < E) ? ei[eid] : (eid - E);
        }
        for (int idx = tid; idx < cn * H; idx += 256) {
            int i = idx / H, h = idx - i * H;
            int eid = g_csr[cs + i];
            sh_alpha[i * H + h] = expf(e[(size_t)eid * H + h] - sh_m[h]) / sh_s[h];
        }
        __syncthreads();
        for (int i = 0; i < cn; i++) {
            const float* row = xp + (size_t)sh_src[i] * D;
            acc0 += sh_alpha[i * H + h0] * row[tid];
            acc1 += sh_alpha[i * H + h1] * row[tid + 256];
        }
        __syncthreads();
    }

    if (mode == 0) {
        float v0 = acc0 + bias[tid];
        float v1 = acc1 + bias[tid + 256];
        out[(size_t)n * D + tid]       = v0 > 0.f ? v0 : expm1f(v0);
        out[(size_t)n * D + tid + 256] = v1 > 0.f ? v1 : expm1f(v1);
    } else {
        sh_red[tid] = acc0;
        sh_red[tid + 256] = acc1;
        __syncthreads();
        if (tid < C) {
            float s = 0.f;
            for (int h = 0; h < H; h++) s += sh_red[h * C + tid];
            out[(size_t)n * C + tid] = s / (float)H + bias[tid];
        }
    }
}

// ---------------- loss --------------------------------------------------------
__global__ void copy_out_kernel(float* __restrict__ dst, int count) {
    int i = blockIdx.x * blockDim.x + threadIdx.x;
    if (i < count) dst[i] = g_logits[i];
}

__global__ __launch_bounds__(128)
void loss_kernel(const int* __restrict__ y, const int* __restrict__ mask, int N) {
    __shared__ float red[128];
    int tid = threadIdx.x;
    float lce = 0.f, lw = 0.f;
    int byte_mode = g_mask_byte;
    for (int n = blockIdx.x; n < N; n += gridDim.x) {
        float v = g_logits[(size_t)n * C2v + tid];
        red[tid] = v;
        __syncthreads();
        #pragma unroll
        for (int o = 64; o; o >>= 1) {
            if (tid < o) red[tid] = fmaxf(red[tid], red[tid + o]);
            __syncthreads();
        }
        float m = red[0];
        __syncthreads();
        red[tid] = expf(v - m);
        __syncthreads();
        #pragma unroll
        for (int o = 64; o; o >>= 1) {
            if (tid < o) red[tid] += red[tid + o];
            __syncthreads();
        }
        if (tid == 0) {
            bool mv = byte_mode ? (((const unsigned char*)mask)[n] != 0) : (mask[n] != 0);
            if (mv) {
                float lse = m + logf(red[0]);
                lce += lse - g_logits[(size_t)n * C2v + y[n]];
                lw += 1.f;
            }
        }
        __syncthreads();
    }
    if (tid == 0) {
        atomicAdd(&g_accum[0], lce);
        atomicAdd(&g_accum[1], lw);
    }
}

__global__ void finalize_kernel(float* d_out, int write_loss) {
    if (write_loss) d_out[0] = g_accum[0] / g_accum[1];
}

// ---------------- launch ------------------------------------------------------
extern "C" void kernel_launch(void* const* d_in, const int* in_sizes, int n_in,
                              void* d_out, int out_size) {
    const float* x       = (const float*)d_in[0];
    const int*   ei      = (const int*)d_in[1];
    const int*   y       = (const int*)d_in[2];
    const int*   mask    = (const int*)d_in[3];
    const float* W1      = (const float*)d_in[4];
    const float* att_s1  = (const float*)d_in[5];
    const float* att_d1  = (const float*)d_in[6];
    const float* b1      = (const float*)d_in[7];
    const float* W2      = (const float*)d_in[8];
    const float* att_s2  = (const float*)d_in[9];
    const float* att_d2  = (const float*)d_in[10];
    const float* b2      = (const float*)d_in[11];
    float* out_f = (float*)d_out;

    int N = in_sizes[0] / D;        // 20000
    int E = in_sizes[1] / 2;        // 100000
    int EP = E + N;

    float *p_xp, *p_h, *p_asrc, *p_adst, *p_e, *p_logits;
    __nv_bfloat16 *p_Ahi, *p_Alo, *p_Bhi, *p_Blo;
    cudaGetSymbolAddress((void**)&p_xp, g_xp);
    cudaGetSymbolAddress((void**)&p_h, g_h);
    cudaGetSymbolAddress((void**)&p_asrc, g_asrc);
    cudaGetSymbolAddress((void**)&p_adst, g_adst);
    cudaGetSymbolAddress((void**)&p_e, g_e);
    cudaGetSymbolAddress((void**)&p_logits, g_logits);
    cudaGetSymbolAddress((void**)&p_Ahi, g_Ahi);
    cudaGetSymbolAddress((void**)&p_Alo, g_Alo);
    cudaGetSymbolAddress((void**)&p_Bhi, g_Bhi);
    cudaGetSymbolAddress((void**)&p_Blo, g_Blo);

    cudaFuncSetAttribute(gemm_mma_kernel,
                         cudaFuncAttributeMaxDynamicSharedMemorySize, GEMM_SMEM);

    int has_loss = (out_size == N * C2v + 1) ? 1 : 0;
    int out_count = out_size - has_loss;
    if (out_count > N * C2v) out_count = N * C2v;

    // --- CSR build (shared by both layers) ---
    init_kernel<<<(N + 255) / 256, 256>>>(N);
    detect_mask_kernel<<<(N / 4 + 255) / 256, 256>>>((const unsigned int*)mask, N / 4);
    hist_kernel<<<(EP + 255) / 256, 256>>>(ei, E, N);
    offsets_kernel<<<(N + 255) / 256, 256>>>(N);
    scatter_kernel<<<(EP + 255) / 256, 256>>>(ei, E, N);

    dim3 ggrid(D / 128, (N + 127) / 128);

    // --- layer 1 ---
    split_kernel<<<592, 256>>>(x, p_Ahi, p_Alo, N * D);
    split_kernel<<<256, 256>>>(W1, p_Bhi, p_Blo, D * D);
    gemm_mma_kernel<<<ggrid, 256, GEMM_SMEM>>>(p_Ahi, p_Alo, p_Bhi, p_Blo, p_xp, N);
    att_kernel<<<(N + 7) / 8, 256>>>(p_xp, att_s1, att_d1, p_asrc, p_adst, N, H1v, C1v);
    score_kernel<<<(EP + 255) / 256, 256>>>(p_asrc, p_adst, ei, E, N, H1v);
    agg_kernel<<<N, 256>>>(p_xp, p_e, b1, p_h, ei, E, H1v, C1v, 0);

    // --- layer 2 ---
    split_kernel<<<592, 256>>>(p_h, p_Ahi, p_Alo, N * D);
    split_kernel<<<256, 256>>>(W2, p_Bhi, p_Blo, D * D);
    gemm_mma_kernel<<<ggrid, 256, GEMM_SMEM>>>(p_Ahi, p_Alo, p_Bhi, p_Blo, p_xp, N);
    att_kernel<<<(N + 7) / 8, 256>>>(p_xp, att_s2, att_d2, p_asrc, p_adst, N, H2v, C2v);
    score_kernel<<<(EP + 255) / 256, 256>>>(p_asrc, p_adst, ei, E, N, H2v);
    agg_kernel<<<N, 256>>>(p_xp, p_e, b2, p_logits, ei, E, H2v, C2v, 1);

    // --- output + loss ---
    copy_out_kernel<<<(out_count + 255) / 256, 256>>>(out_f + has_loss, out_count);
    loss_kernel<<<1024, 128>>>(y, mask, N);
    finalize_kernel<<<1, 1>>>(out_f, has_loss);
}

// round 7
// speedup vs baseline: 1.0076x; 1.0076x over previous
#include <cuda_runtime.h>
#include <cuda_bf16.h>
#include <math.h>
#include <stdint.h>

// Problem constants
#define D      512
#define NNODES 20000
#define NEDGES 100000
#define EPRIME (NEDGES + NNODES)
#define H1v    8
#define C1v    64
#define H2v    4
#define C2v    128
#define CHUNK  256

// ---------------- scratch (device globals; no allocation allowed) -------------
__device__ float g_xp[(size_t)NNODES * D];
__device__ float g_h[(size_t)NNODES * D];
__device__ float g_asrc[(size_t)NNODES * H1v];
__device__ float g_adst[(size_t)NNODES * H1v];
__device__ float g_e[(size_t)EPRIME * H1v];
__device__ int   g_deg[NNODES];
__device__ int   g_rowstart[NNODES];
__device__ int   g_cursor[NNODES];
__device__ int   g_csr[EPRIME];
__device__ float g_accum[2];
__device__ int   g_mask_byte;
__device__ int   g_total;
__device__ __nv_bfloat16 g_Ahi[(size_t)NNODES * D];
__device__ __nv_bfloat16 g_Alo[(size_t)NNODES * D];
__device__ __nv_bfloat16 g_Bhi[(size_t)D * D];
__device__ __nv_bfloat16 g_Blo[(size_t)D * D];

// ---------------- helpers ----------------------------------------------------
__device__ __forceinline__ float warp_max(float v) {
    #pragma unroll
    for (int o = 16; o; o >>= 1) v = fmaxf(v, __shfl_xor_sync(0xffffffffu, v, o));
    return v;
}
__device__ __forceinline__ float warp_sum(float v) {
    #pragma unroll
    for (int o = 16; o; o >>= 1) v += __shfl_xor_sync(0xffffffffu, v, o);
    return v;
}

__device__ __forceinline__ void mma16816(float* c, const uint32_t* a, const uint32_t* b) {
    asm volatile(
        "mma.sync.aligned.m16n8k16.row.col.f32.bf16.bf16.f32 "
        "{%0,%1,%2,%3}, {%4,%5,%6,%7}, {%8,%9}, {%0,%1,%2,%3};\n"
        : "+f"(c[0]), "+f"(c[1]), "+f"(c[2]), "+f"(c[3])
        : "r"(a[0]), "r"(a[1]), "r"(a[2]), "r"(a[3]), "r"(b[0]), "r"(b[1]));
}
__device__ __forceinline__ void ldsm4(uint32_t* r, uint32_t addr) {
    asm volatile("ldmatrix.sync.aligned.m8n8.x4.shared.b16 {%0,%1,%2,%3}, [%4];\n"
        : "=r"(r[0]), "=r"(r[1]), "=r"(r[2]), "=r"(r[3]) : "r"(addr));
}
__device__ __forceinline__ void ldsm4t(uint32_t* r, uint32_t addr) {
    asm volatile("ldmatrix.sync.aligned.m8n8.x4.trans.shared.b16 {%0,%1,%2,%3}, [%4];\n"
        : "=r"(r[0]), "=r"(r[1]), "=r"(r[2]), "=r"(r[3]) : "r"(addr));
}
__device__ __forceinline__ void cpasync16(uint32_t dst, const void* src, int srcsize) {
    asm volatile("cp.async.cg.shared.global [%0], [%1], 16, %2;\n"
        :: "r"(dst), "l"(src), "r"(srcsize));
}
__device__ __forceinline__ void cp_commit() { asm volatile("cp.async.commit_group;\n"); }
template<int NW> __device__ __forceinline__ void cp_wait() {
    asm volatile("cp.async.wait_group %0;\n" :: "n"(NW));
}

// ---------------- init / CSR build -------------------------------------------
__global__ void init_kernel(const unsigned int* __restrict__ m, int nwords, int N) {
    int i = blockIdx.x * blockDim.x + threadIdx.x;
    if (i < N) g_deg[i] = 0;
    if (i < nwords) {
        unsigned v = m[i];
        if (v != 0u && v != 1u && v != 0x3F800000u) atomicOr(&g_mask_byte, 1);
    }
    if (i == 0) { g_accum[0] = 0.f; g_accum[1] = 0.f; g_total = 0; }
}
__global__ void zero_flags_kernel() { g_mask_byte = 0; }

__global__ void hist_kernel(const int* __restrict__ ei, int E, int N) {
    int i = blockIdx.x * blockDim.x + threadIdx.x;
    if (i >= E + N) return;
    int d = (i < E) ? ei[E + i] : (i - E);
    atomicAdd(&g_deg[d], 1);
}
__global__ void offsets_kernel(int N) {
    int i = blockIdx.x * blockDim.x + threadIdx.x;
    if (i < N) {
        int base = atomicAdd(&g_total, g_deg[i]);
        g_rowstart[i] = base;
        g_cursor[i] = base;
    }
}
__global__ void scatter_kernel(const int* __restrict__ ei, int E, int N) {
    int i = blockIdx.x * blockDim.x + threadIdx.x;
    if (i >= E + N) return;
    int d = (i < E) ? ei[E + i] : (i - E);
    int pos = atomicAdd(&g_cursor[d], 1);
    g_csr[pos] = i;
}

// ---------------- bf16 hi/lo split ---------------------------------------------
__global__ void split_kernel(const float* __restrict__ x,
                             __nv_bfloat16* __restrict__ hi,
                             __nv_bfloat16* __restrict__ lo, int n) {
    for (int i = blockIdx.x * blockDim.x + threadIdx.x; i < n; i += gridDim.x * blockDim.x) {
        float v = x[i];
        __nv_bfloat16 h = __float2bfloat16(v);
        hi[i] = h;
        lo[i] = __float2bfloat16(v - __bfloat162float(h));
    }
}

// ---------------- tensor-core GEMM: C[M,512] = A[M,512] @ B[512,512] -----------
// bf16 hi/lo split, 3 products, mma.m16n8k16, 3-stage cp.async pipeline.
#define LDA_S 40     // 32 + 8 pad (elems)
#define LDB_S 136    // 128 + 8 pad (elems)
#define A_HI_OFF 0
#define A_LO_OFF (128 * LDA_S * 2)                    // 10240
#define B_HI_OFF (A_LO_OFF * 2)                       // 20480
#define B_LO_OFF (B_HI_OFF + 32 * LDB_S * 2)          // 29184
#define STAGE_BYTES (B_LO_OFF + 32 * LDB_S * 2)       // 37888
#define NSTAGE 3
#define GEMM_SMEM (NSTAGE * STAGE_BYTES)              // 113664

extern __shared__ char smem_raw[];

__global__ __launch_bounds__(256, 1)
void gemm_mma_kernel(const __nv_bfloat16* __restrict__ Ahi,
                     const __nv_bfloat16* __restrict__ Alo,
                     const __nv_bfloat16* __restrict__ Bhi,
                     const __nv_bfloat16* __restrict__ Blo,
                     float* __restrict__ C, int M) {
    const int tid = threadIdx.x;
    const int lane = tid & 31;
    const int wid = tid >> 5;
    const int m0 = blockIdx.y * 128;
    const int n0 = blockIdx.x * 128;
    const int warp_m = wid >> 2;          // 0..1 -> 64 rows
    const int warp_n = wid & 3;           // 0..3 -> 32 cols
    const int m_base = warp_m * 64;
    const int n_base = warp_n * 32;

    uint32_t smem_u32 = (uint32_t)__cvta_generic_to_shared(smem_raw);

    const int arow0 = tid >> 2, acol0 = (tid & 3) * 8;
    const int brow0 = tid >> 4, bcol0 = (tid & 15) * 8;

    float acc[4][4][4];
    #pragma unroll
    for (int i = 0; i < 4; i++)
        #pragma unroll
        for (int j = 0; j < 4; j++)
            #pragma unroll
            for (int k = 0; k < 4; k++) acc[i][j][k] = 0.f;

    const int NIT = D / 32;   // 16

    auto load_stage = [&](int it, int s) {
        int k0 = it * 32;
        uint32_t base = smem_u32 + s * STAGE_BYTES;
        #pragma unroll
        for (int c = 0; c < 2; c++) {
            int row = arow0 + c * 64;
            int gr = m0 + row;
            int ok = (gr < M) ? 16 : 0;
            size_t goff = (size_t)gr * D + k0 + acol0;
            uint32_t soff = (uint32_t)(row * LDA_S + acol0) * 2;
            cpasync16(base + A_HI_OFF + soff, Ahi + goff, ok);
            cpasync16(base + A_LO_OFF + soff, Alo + goff, ok);
        }
        #pragma unroll
        for (int c = 0; c < 2; c++) {
            int row = brow0 + c * 16;
            size_t goff = (size_t)(k0 + row) * D + n0 + bcol0;
            uint32_t soff = (uint32_t)(row * LDB_S + bcol0) * 2;
            cpasync16(base + B_HI_OFF + soff, Bhi + goff, 16);
            cpasync16(base + B_LO_OFF + soff, Blo + goff, 16);
        }
        cp_commit();
    };

    load_stage(0, 0);
    load_stage(1, 1);

    for (int it = 0; it < NIT; it++) {
        if (it < NIT - 1) cp_wait<1>(); else cp_wait<0>();
        __syncthreads();
        if (it + 2 < NIT) load_stage(it + 2, (it + 2) % NSTAGE);

        uint32_t stg = smem_u32 + (it % NSTAGE) * STAGE_BYTES;
        #pragma unroll
        for (int kk = 0; kk < 2; kk++) {
            int kof = kk * 16;
            uint32_t ahi[4][4], alo[4][4];
            #pragma unroll
            for (int mt = 0; mt < 4; mt++) {
                uint32_t off = (uint32_t)((m_base + mt * 16 + (lane & 15)) * LDA_S
                                          + kof + 8 * (lane >> 4)) * 2;
                ldsm4(ahi[mt], stg + A_HI_OFF + off);
                ldsm4(alo[mt], stg + A_LO_OFF + off);
            }
            uint32_t bhi[4][2], blo[4][2];
            #pragma unroll
            for (int p = 0; p < 2; p++) {
                uint32_t off = (uint32_t)((kof + (lane & 7) + 8 * ((lane >> 3) & 1)) * LDB_S
                                          + n_base + p * 16 + 8 * (lane >> 4)) * 2;
                uint32_t r[4];
                ldsm4t(r, stg + B_HI_OFF + off);
                bhi[p * 2][0] = r[0]; bhi[p * 2][1] = r[1];
                bhi[p * 2 + 1][0] = r[2]; bhi[p * 2 + 1][1] = r[3];
                ldsm4t(r, stg + B_LO_OFF + off);
                blo[p * 2][0] = r[0]; blo[p * 2][1] = r[1];
                blo[p * 2 + 1][0] = r[2]; blo[p * 2 + 1][1] = r[3];
            }
            #pragma unroll
            for (int mt = 0; mt < 4; mt++)
                #pragma unroll
                for (int nt = 0; nt < 4; nt++) {
                    mma16816(acc[mt][nt], ahi[mt], bhi[nt]);
                    mma16816(acc[mt][nt], ahi[mt], blo[nt]);
                    mma16816(acc[mt][nt], alo[mt], bhi[nt]);
                }
        }
    }

    // epilogue
    const int gid = lane >> 2, t4 = lane & 3;
    #pragma unroll
    for (int mt = 0; mt < 4; mt++) {
        int r0 = m0 + m_base + mt * 16 + gid;
        int r1 = r0 + 8;
        #pragma unroll
        for (int nt = 0; nt < 4; nt++) {
            int col = n0 + n_base + nt * 8 + t4 * 2;
            if (r0 < M) *(float2*)&C[(size_t)r0 * D + col] = make_float2(acc[mt][nt][0], acc[mt][nt][1]);
            if (r1 < M) *(float2*)&C[(size_t)r1 * D + col] = make_float2(acc[mt][nt][2], acc[mt][nt][3]);
        }
    }
}

// ---------------- per-node attention dot products ----------------------------
__global__ void att_kernel(const float* __restrict__ xp,
                           const float* __restrict__ a_src, const float* __restrict__ a_dst,
                           float* __restrict__ asrc, float* __restrict__ adst,
                           int N, int H, int C) {
    int warp = (blockIdx.x * blockDim.x + threadIdx.x) >> 5;
    int lane = threadIdx.x & 31;
    if (warp >= N) return;
    const float* row = xp + (size_t)warp * D;
    for (int h = 0; h < H; h++) {
        float ss = 0.f, sd = 0.f;
        for (int j = lane; j < C; j += 32) {
            float xv = row[h * C + j];
            ss += xv * a_src[h * C + j];
            sd += xv * a_dst[h * C + j];
        }
        ss = warp_sum(ss);
        sd = warp_sum(sd);
        if (lane == 0) { asrc[warp * H + h] = ss; adst[warp * H + h] = sd; }
    }
}

// ---------------- per-edge leaky-relu scores ---------------------------------
__global__ void score_kernel(const float* __restrict__ asrc, const float* __restrict__ adst,
                             const int* __restrict__ ei, int E, int N, int H) {
    int i = blockIdx.x * blockDim.x + threadIdx.x;
    if (i >= E + N) return;
    int s, d;
    if (i < E) { s = ei[i]; d = ei[E + i]; } else { s = d = i - E; }
    for (int h = 0; h < H; h++) {
        float v = asrc[s * H + h] + adst[d * H + h];
        g_e[(size_t)i * H + h] = v > 0.f ? v : 0.2f * v;
    }
}

// ---------------- per-dst softmax + aggregate (block per node) ---------------
__global__ __launch_bounds__(256)
void agg_kernel(const float* __restrict__ xp, const float* __restrict__ e,
                const float* __restrict__ bias, float* __restrict__ out,
                const int* __restrict__ ei, int E, int H, int C, int mode) {
    __shared__ float sh_alpha[CHUNK * H1v];
    __shared__ int   sh_src[CHUNK];
    __shared__ float sh_m[H1v], sh_s[H1v];
    __shared__ float sh_red[512];
    int n = blockIdx.x;
    int tid = threadIdx.x;
    int w = tid >> 5, lane = tid & 31;
    int beg = g_rowstart[n], end = beg + g_deg[n];

    if (w < H) {
        float m = -1e30f;
        for (int i = beg + lane; i < end; i += 32)
            m = fmaxf(m, e[(size_t)g_csr[i] * H + w]);
        m = warp_max(m);
        float s = 0.f;
        for (int i = beg + lane; i < end; i += 32)
            s += expf(e[(size_t)g_csr[i] * H + w] - m);
        s = warp_sum(s);
        if (lane == 0) { sh_m[w] = m; sh_s[w] = s + 1e-16f; }
    }
    __syncthreads();

    int h0 = tid / C, h1 = (tid + 256) / C;
    float acc0 = 0.f, acc1 = 0.f;
    for (int cs = beg; cs < end; cs += CHUNK) {
        int cn = min(CHUNK, end - cs);
        for (int idx = tid; idx < cn; idx += 256) {
            int eid = g_csr[cs + idx];
            sh_src[idx] = (eid < E) ? ei[eid] : (eid - E);
        }
        for (int idx = tid; idx < cn * H; idx += 256) {
            int i = idx / H, h = idx - i * H;
            int eid = g_csr[cs + i];
            sh_alpha[i * H + h] = expf(e[(size_t)eid * H + h] - sh_m[h]) / sh_s[h];
        }
        __syncthreads();
        for (int i = 0; i < cn; i++) {
            const float* row = xp + (size_t)sh_src[i] * D;
            acc0 += sh_alpha[i * H + h0] * row[tid];
            acc1 += sh_alpha[i * H + h1] * row[tid + 256];
        }
        __syncthreads();
    }

    if (mode == 0) {
        float v0 = acc0 + bias[tid];
        float v1 = acc1 + bias[tid + 256];
        out[(size_t)n * D + tid]       = v0 > 0.f ? v0 : expm1f(v0);
        out[(size_t)n * D + tid + 256] = v1 > 0.f ? v1 : expm1f(v1);
    } else {
        sh_red[tid] = acc0;
        sh_red[tid + 256] = acc1;
        __syncthreads();
        if (tid < C) {
            float s = 0.f;
            for (int h = 0; h < H; h++) s += sh_red[h * C + tid];
            out[(size_t)n * C + tid] = s / (float)H + bias[tid];
        }
    }
}

// ---------------- loss ---------------------------------------------------------
__global__ __launch_bounds__(128)
void loss_kernel(const float* __restrict__ logits,
                 const int* __restrict__ y, const int* __restrict__ mask, int N) {
    __shared__ float red[128];
    int tid = threadIdx.x;
    float lce = 0.f, lw = 0.f;
    int byte_mode = g_mask_byte;
    for (int n = blockIdx.x; n < N; n += gridDim.x) {
        float v = logits[(size_t)n * C2v + tid];
        red[tid] = v;
        __syncthreads();
        #pragma unroll
        for (int o = 64; o; o >>= 1) {
            if (tid < o) red[tid] = fmaxf(red[tid], red[tid + o]);
            __syncthreads();
        }
        float m = red[0];
        __syncthreads();
        red[tid] = expf(v - m);
        __syncthreads();
        #pragma unroll
        for (int o = 64; o; o >>= 1) {
            if (tid < o) red[tid] += red[tid + o];
            __syncthreads();
        }
        if (tid == 0) {
            bool mv = byte_mode ? (((const unsigned char*)mask)[n] != 0) : (mask[n] != 0);
            if (mv) {
                float lse = m + logf(red[0]);
                lce += lse - logits[(size_t)n * C2v + y[n]];
                lw += 1.f;
            }
        }
        __syncthreads();
    }
    if (tid == 0) {
        atomicAdd(&g_accum[0], lce);
        atomicAdd(&g_accum[1], lw);
    }
}

__global__ void finalize_kernel(float* d_out, int write_loss) {
    if (write_loss) d_out[0] = g_accum[0] / g_accum[1];
}

// ---------------- launch --------------------------------------------------------
extern "C" void kernel_launch(void* const* d_in, const int* in_sizes, int n_in,
                              void* d_out, int out_size) {
    const float* x       = (const float*)d_in[0];
    const int*   ei      = (const int*)d_in[1];
    const int*   y       = (const int*)d_in[2];
    const int*   mask    = (const int*)d_in[3];
    const float* W1      = (const float*)d_in[4];
    const float* att_s1  = (const float*)d_in[5];
    const float* att_d1  = (const float*)d_in[6];
    const float* b1      = (const float*)d_in[7];
    const float* W2      = (const float*)d_in[8];
    const float* att_s2  = (const float*)d_in[9];
    const float* att_d2  = (const float*)d_in[10];
    const float* b2      = (const float*)d_in[11];
    float* out_f = (float*)d_out;

    int N = in_sizes[0] / D;        // 20000
    int E = in_sizes[1] / 2;        // 100000
    int EP = E + N;

    float *p_xp, *p_h, *p_asrc, *p_adst, *p_e;
    __nv_bfloat16 *p_Ahi, *p_Alo, *p_Bhi, *p_Blo;
    cudaGetSymbolAddress((void**)&p_xp, g_xp);
    cudaGetSymbolAddress((void**)&p_h, g_h);
    cudaGetSymbolAddress((void**)&p_asrc, g_asrc);
    cudaGetSymbolAddress((void**)&p_adst, g_adst);
    cudaGetSymbolAddress((void**)&p_e, g_e);
    cudaGetSymbolAddress((void**)&p_Ahi, g_Ahi);
    cudaGetSymbolAddress((void**)&p_Alo, g_Alo);
    cudaGetSymbolAddress((void**)&p_Bhi, g_Bhi);
    cudaGetSymbolAddress((void**)&p_Blo, g_Blo);

    cudaFuncSetAttribute(gemm_mma_kernel,
                         cudaFuncAttributeMaxDynamicSharedMemorySize, GEMM_SMEM);

    int has_loss = (out_size == N * C2v + 1) ? 1 : 0;
    float* p_logits = out_f + has_loss;

    // --- CSR build (shared by both layers) ---
    zero_flags_kernel<<<1, 1>>>();
    init_kernel<<<(N + 255) / 256, 256>>>((const unsigned int*)mask, N / 4, N);
    hist_kernel<<<(EP + 255) / 256, 256>>>(ei, E, N);
    offsets_kernel<<<(N + 255) / 256, 256>>>(N);
    scatter_kernel<<<(EP + 255) / 256, 256>>>(ei, E, N);

    dim3 ggrid(D / 128, (N + 127) / 128);

    // --- layer 1 ---
    split_kernel<<<592, 256>>>(x, p_Ahi, p_Alo, N * D);
    split_kernel<<<256, 256>>>(W1, p_Bhi, p_Blo, D * D);
    gemm_mma_kernel<<<ggrid, 256, GEMM_SMEM>>>(p_Ahi, p_Alo, p_Bhi, p_Blo, p_xp, N);
    att_kernel<<<(N + 7) / 8, 256>>>(p_xp, att_s1, att_d1, p_asrc, p_adst, N, H1v, C1v);
    score_kernel<<<(EP + 255) / 256, 256>>>(p_asrc, p_adst, ei, E, N, H1v);
    agg_kernel<<<N, 256>>>(p_xp, p_e, b1, p_h, ei, E, H1v, C1v, 0);

    // --- layer 2 ---
    split_kernel<<<592, 256>>>(p_h, p_Ahi, p_Alo, N * D);
    split_kernel<<<256, 256>>>(W2, p_Bhi, p_Blo, D * D);
    gemm_mma_kernel<<<ggrid, 256, GEMM_SMEM>>>(p_Ahi, p_Alo, p_Bhi, p_Blo, p_xp, N);
    att_kernel<<<(N + 7) / 8, 256>>>(p_xp, att_s2, att_d2, p_asrc, p_adst, N, H2v, C2v);
    score_kernel<<<(EP + 255) / 256, 256>>>(p_asrc, p_adst, ei, E, N, H2v);
    agg_kernel<<<N, 256>>>(p_xp, p_e, b2, p_logits, ei, E, H2v, C2v, 1);

    // --- loss ---
    loss_kernel<<<1024, 128>>>(p_logits, y, mask, N);
    finalize_kernel<<<1, 1>>>(out_f, has_loss);
}

// round 8
// speedup vs baseline: 1.1408x; 1.1323x over previous
#include <cuda_runtime.h>
#include <cuda_bf16.h>
#include <math.h>
#include <stdint.h>

// Problem constants
#define D      512
#define NNODES 20000
#define NEDGES 100000
#define EPRIME (NEDGES + NNODES)
#define H1v    8
#define C1v    64
#define H2v    4
#define C2v    128
#define CHUNK  256

// ---------------- scratch (device globals; no allocation allowed) -------------
__device__ float g_xp[(size_t)NNODES * D];
__device__ float g_asrc[(size_t)NNODES * H1v];
__device__ float g_adst[(size_t)NNODES * H1v];
__device__ float g_e[(size_t)EPRIME * H1v];
__device__ int   g_deg[NNODES];
__device__ int   g_rowstart[NNODES];
__device__ int   g_cursor[NNODES];
__device__ int   g_csr[EPRIME];
__device__ float g_accum[2];
__device__ int   g_mask_byte;
__device__ int   g_total;
__device__ __nv_bfloat16 g_Ahi[(size_t)NNODES * D];
__device__ __nv_bfloat16 g_Alo[(size_t)NNODES * D];
__device__ __nv_bfloat16 g_Bhi[(size_t)D * D];
__device__ __nv_bfloat16 g_Blo[(size_t)D * D];

// ---------------- helpers ----------------------------------------------------
__device__ __forceinline__ float warp_max(float v) {
    #pragma unroll
    for (int o = 16; o; o >>= 1) v = fmaxf(v, __shfl_xor_sync(0xffffffffu, v, o));
    return v;
}
__device__ __forceinline__ float warp_sum(float v) {
    #pragma unroll
    for (int o = 16; o; o >>= 1) v += __shfl_xor_sync(0xffffffffu, v, o);
    return v;
}

__device__ __forceinline__ void mma16816(float* c, const uint32_t* a, const uint32_t* b) {
    asm volatile(
        "mma.sync.aligned.m16n8k16.row.col.f32.bf16.bf16.f32 "
        "{%0,%1,%2,%3}, {%4,%5,%6,%7}, {%8,%9}, {%0,%1,%2,%3};\n"
        : "+f"(c[0]), "+f"(c[1]), "+f"(c[2]), "+f"(c[3])
        : "r"(a[0]), "r"(a[1]), "r"(a[2]), "r"(a[3]), "r"(b[0]), "r"(b[1]));
}
__device__ __forceinline__ void ldsm4(uint32_t* r, uint32_t addr) {
    asm volatile("ldmatrix.sync.aligned.m8n8.x4.shared.b16 {%0,%1,%2,%3}, [%4];\n"
        : "=r"(r[0]), "=r"(r[1]), "=r"(r[2]), "=r"(r[3]) : "r"(addr));
}
__device__ __forceinline__ void ldsm4t(uint32_t* r, uint32_t addr) {
    asm volatile("ldmatrix.sync.aligned.m8n8.x4.trans.shared.b16 {%0,%1,%2,%3}, [%4];\n"
        : "=r"(r[0]), "=r"(r[1]), "=r"(r[2]), "=r"(r[3]) : "r"(addr));
}
__device__ __forceinline__ void cpasync16(uint32_t dst, const void* src, int srcsize) {
    asm volatile("cp.async.cg.shared.global [%0], [%1], 16, %2;\n"
        :: "r"(dst), "l"(src), "r"(srcsize));
}
__device__ __forceinline__ void cp_commit() { asm volatile("cp.async.commit_group;\n"); }
template<int NW> __device__ __forceinline__ void cp_wait() {
    asm volatile("cp.async.wait_group %0;\n" :: "n"(NW));
}

// ---------------- init / CSR build -------------------------------------------
__global__ void init_kernel(int N) {
    int i = blockIdx.x * blockDim.x + threadIdx.x;
    if (i < N) g_deg[i] = 0;
    if (i == 0) { g_accum[0] = 0.f; g_accum[1] = 0.f; g_total = 0; g_mask_byte = 0; }
}

// histogram of destinations + mask dtype detection (fused)
__global__ void hist_kernel(const int* __restrict__ ei,
                            const unsigned int* __restrict__ m, int nwords,
                            int E, int N) {
    int i = blockIdx.x * blockDim.x + threadIdx.x;
    if (i < nwords) {
        unsigned v = m[i];
        if (v != 0u && v != 1u && v != 0x3F800000u) atomicOr(&g_mask_byte, 1);
    }
    if (i >= E + N) return;
    int d = (i < E) ? ei[E + i] : (i - E);
    atomicAdd(&g_deg[d], 1);
}
__global__ void offsets_kernel(int N) {
    int i = blockIdx.x * blockDim.x + threadIdx.x;
    if (i < N) {
        int base = atomicAdd(&g_total, g_deg[i]);
        g_rowstart[i] = base;
        g_cursor[i] = base;
    }
}
__global__ void scatter_kernel(const int* __restrict__ ei, int E, int N) {
    int i = blockIdx.x * blockDim.x + threadIdx.x;
    if (i >= E + N) return;
    int d = (i < E) ? ei[E + i] : (i - E);
    int pos = atomicAdd(&g_cursor[d], 1);
    g_csr[pos] = i;
}

// ---------------- bf16 hi/lo split ---------------------------------------------
__global__ void split_kernel(const float* __restrict__ x,
                             __nv_bfloat16* __restrict__ hi,
                             __nv_bfloat16* __restrict__ lo, int n) {
    for (int i = blockIdx.x * blockDim.x + threadIdx.x; i < n; i += gridDim.x * blockDim.x) {
        float v = x[i];
        __nv_bfloat16 h = __float2bfloat16(v);
        hi[i] = h;
        lo[i] = __float2bfloat16(v - __bfloat162float(h));
    }
}

// ---------------- tensor-core GEMM: C[M,512] = A[M,512] @ B[512,512] -----------
// bf16 hi/lo split, 3 products, mma.m16n8k16, 2-stage cp.async, 2 CTAs/SM.
#define LDA_S 40     // 32 + 8 pad (elems)
#define LDB_S 136    // 128 + 8 pad (elems)
#define A_HI_OFF 0
#define A_LO_OFF (128 * LDA_S * 2)                    // 10240
#define B_HI_OFF (A_LO_OFF * 2)                       // 20480
#define B_LO_OFF (B_HI_OFF + 32 * LDB_S * 2)          // 29184
#define STAGE_BYTES (B_LO_OFF + 32 * LDB_S * 2)       // 37888
#define GEMM_SMEM (2 * STAGE_BYTES)                   // 75776

extern __shared__ char smem_raw[];

__global__ __launch_bounds__(256, 2)
void gemm_mma_kernel(const __nv_bfloat16* __restrict__ Ahi,
                     const __nv_bfloat16* __restrict__ Alo,
                     const __nv_bfloat16* __restrict__ Bhi,
                     const __nv_bfloat16* __restrict__ Blo,
                     float* __restrict__ C, int M) {
    const int tid = threadIdx.x;
    const int lane = tid & 31;
    const int wid = tid >> 5;
    const int m0 = blockIdx.y * 128;
    const int n0 = blockIdx.x * 128;
    const int m_base = (wid >> 2) * 64;
    const int n_base = (wid & 3) * 32;

    uint32_t smem_u32 = (uint32_t)__cvta_generic_to_shared(smem_raw);

    const int arow0 = tid >> 2, acol0 = (tid & 3) * 8;
    const int brow0 = tid >> 4, bcol0 = (tid & 15) * 8;

    float acc[4][4][4];
    #pragma unroll
    for (int i = 0; i < 4; i++)
        #pragma unroll
        for (int j = 0; j < 4; j++)
            #pragma unroll
            for (int k = 0; k < 4; k++) acc[i][j][k] = 0.f;

    const int NIT = D / 32;   // 16

    auto load_stage = [&](int it, int s) {
        int k0 = it * 32;
        uint32_t base = smem_u32 + s * STAGE_BYTES;
        #pragma unroll
        for (int c = 0; c < 2; c++) {
            int row = arow0 + c * 64;
            int gr = m0 + row;
            int ok = (gr < M) ? 16 : 0;
            size_t goff = (size_t)gr * D + k0 + acol0;
            uint32_t soff = (uint32_t)(row * LDA_S + acol0) * 2;
            cpasync16(base + A_HI_OFF + soff, Ahi + goff, ok);
            cpasync16(base + A_LO_OFF + soff, Alo + goff, ok);
        }
        #pragma unroll
        for (int c = 0; c < 2; c++) {
            int row = brow0 + c * 16;
            size_t goff = (size_t)(k0 + row) * D + n0 + bcol0;
            uint32_t soff = (uint32_t)(row * LDB_S + bcol0) * 2;
            cpasync16(base + B_HI_OFF + soff, Bhi + goff, 16);
            cpasync16(base + B_LO_OFF + soff, Blo + goff, 16);
        }
        cp_commit();
    };

    load_stage(0, 0);

    for (int it = 0; it < NIT; it++) {
        if (it + 1 < NIT) {
            load_stage(it + 1, (it + 1) & 1);
            cp_wait<1>();
        } else {
            cp_wait<0>();
        }
        __syncthreads();

        uint32_t stg = smem_u32 + (it & 1) * STAGE_BYTES;
        #pragma unroll
        for (int kk = 0; kk < 2; kk++) {
            int kof = kk * 16;
            // B fragments for this k-slice (16 regs hi + lo)
            uint32_t bhi[4][2], blo[4][2];
            #pragma unroll
            for (int p = 0; p < 2; p++) {
                uint32_t off = (uint32_t)((kof + (lane & 7) + 8 * ((lane >> 3) & 1)) * LDB_S
                                          + n_base + p * 16 + 8 * (lane >> 4)) * 2;
                uint32_t r[4];
                ldsm4t(r, stg + B_HI_OFF + off);
                bhi[p * 2][0] = r[0]; bhi[p * 2][1] = r[1];
                bhi[p * 2 + 1][0] = r[2]; bhi[p * 2 + 1][1] = r[3];
                ldsm4t(r, stg + B_LO_OFF + off);
                blo[p * 2][0] = r[0]; blo[p * 2][1] = r[1];
                blo[p * 2 + 1][0] = r[2]; blo[p * 2 + 1][1] = r[3];
            }
            // A fragments in pairs of m-tiles to bound live registers
            #pragma unroll
            for (int mh = 0; mh < 2; mh++) {
                uint32_t ahi[2][4], alo[2][4];
                #pragma unroll
                for (int q = 0; q < 2; q++) {
                    int mt = mh * 2 + q;
                    uint32_t off = (uint32_t)((m_base + mt * 16 + (lane & 15)) * LDA_S
                                              + kof + 8 * (lane >> 4)) * 2;
                    ldsm4(ahi[q], stg + A_HI_OFF + off);
                    ldsm4(alo[q], stg + A_LO_OFF + off);
                }
                #pragma unroll
                for (int q = 0; q < 2; q++)
                    #pragma unroll
                    for (int nt = 0; nt < 4; nt++) {
                        float* a = acc[mh * 2 + q][nt];
                        mma16816(a, ahi[q], bhi[nt]);
                        mma16816(a, ahi[q], blo[nt]);
                        mma16816(a, alo[q], bhi[nt]);
                    }
            }
        }
        __syncthreads();
    }

    // epilogue
    const int gid = lane >> 2, t4 = lane & 3;
    #pragma unroll
    for (int mt = 0; mt < 4; mt++) {
        int r0 = m0 + m_base + mt * 16 + gid;
        int r1 = r0 + 8;
        #pragma unroll
        for (int nt = 0; nt < 4; nt++) {
            int col = n0 + n_base + nt * 8 + t4 * 2;
            if (r0 < M) *(float2*)&C[(size_t)r0 * D + col] = make_float2(acc[mt][nt][0], acc[mt][nt][1]);
            if (r1 < M) *(float2*)&C[(size_t)r1 * D + col] = make_float2(acc[mt][nt][2], acc[mt][nt][3]);
        }
    }
}

// ---------------- per-node attention dot products ----------------------------
__global__ void att_kernel(const float* __restrict__ xp,
                           const float* __restrict__ a_src, const float* __restrict__ a_dst,
                           float* __restrict__ asrc, float* __restrict__ adst,
                           int N, int H, int C) {
    int warp = (blockIdx.x * blockDim.x + threadIdx.x) >> 5;
    int lane = threadIdx.x & 31;
    if (warp >= N) return;
    const float* row = xp + (size_t)warp * D;
    for (int h = 0; h < H; h++) {
        float ss = 0.f, sd = 0.f;
        for (int j = lane; j < C; j += 32) {
            float xv = row[h * C + j];
            ss += xv * a_src[h * C + j];
            sd += xv * a_dst[h * C + j];
        }
        ss = warp_sum(ss);
        sd = warp_sum(sd);
        if (lane == 0) { asrc[warp * H + h] = ss; adst[warp * H + h] = sd; }
    }
}

// ---------------- per-edge leaky-relu scores ---------------------------------
__global__ void score_kernel(const float* __restrict__ asrc, const float* __restrict__ adst,
                             const int* __restrict__ ei, int E, int N, int H) {
    int i = blockIdx.x * blockDim.x + threadIdx.x;
    if (i >= E + N) return;
    int s, d;
    if (i < E) { s = ei[i]; d = ei[E + i]; } else { s = d = i - E; }
    for (int h = 0; h < H; h++) {
        float v = asrc[s * H + h] + adst[d * H + h];
        g_e[(size_t)i * H + h] = v > 0.f ? v : 0.2f * v;
    }
}

// ---------------- per-dst softmax + aggregate (block per node) ---------------
// mode 0: elu(agg + bias) -> written as bf16 hi/lo (direct GEMM2 input)
// mode 1: mean_h(agg) + bias -> fp32 out (logits)
__global__ __launch_bounds__(256)
void agg_kernel(const float* __restrict__ xp, const float* __restrict__ e,
                const float* __restrict__ bias, float* __restrict__ out,
                __nv_bfloat16* __restrict__ out_hi, __nv_bfloat16* __restrict__ out_lo,
                const int* __restrict__ ei, int E, int H, int C, int mode) {
    __shared__ float sh_alpha[CHUNK * H1v];
    __shared__ int   sh_src[CHUNK];
    __shared__ float sh_m[H1v], sh_s[H1v];
    __shared__ float sh_red[512];
    int n = blockIdx.x;
    int tid = threadIdx.x;
    int w = tid >> 5, lane = tid & 31;
    int beg = g_rowstart[n], end = beg + g_deg[n];

    if (w < H) {
        float m = -1e30f;
        for (int i = beg + lane; i < end; i += 32)
            m = fmaxf(m, e[(size_t)g_csr[i] * H + w]);
        m = warp_max(m);
        float s = 0.f;
        for (int i = beg + lane; i < end; i += 32)
            s += expf(e[(size_t)g_csr[i] * H + w] - m);
        s = warp_sum(s);
        if (lane == 0) { sh_m[w] = m; sh_s[w] = s + 1e-16f; }
    }
    __syncthreads();

    int h0 = tid / C, h1 = (tid + 256) / C;
    float acc0 = 0.f, acc1 = 0.f;
    for (int cs = beg; cs < end; cs += CHUNK) {
        int cn = min(CHUNK, end - cs);
        for (int idx = tid; idx < cn; idx += 256) {
            int eid = g_csr[cs + idx];
            sh_src[idx] = (eid < E) ? ei[eid] : (eid - E);
        }
        for (int idx = tid; idx < cn * H; idx += 256) {
            int i = idx / H, h = idx - i * H;
            int eid = g_csr[cs + i];
            sh_alpha[i * H + h] = expf(e[(size_t)eid * H + h] - sh_m[h]) / sh_s[h];
        }
        __syncthreads();
        for (int i = 0; i < cn; i++) {
            const float* row = xp + (size_t)sh_src[i] * D;
            acc0 += sh_alpha[i * H + h0] * row[tid];
            acc1 += sh_alpha[i * H + h1] * row[tid + 256];
        }
        __syncthreads();
    }

    if (mode == 0) {
        float v0 = acc0 + bias[tid];
        float v1 = acc1 + bias[tid + 256];
        v0 = v0 > 0.f ? v0 : expm1f(v0);
        v1 = v1 > 0.f ? v1 : expm1f(v1);
        __nv_bfloat16 h0b = __float2bfloat16(v0);
        __nv_bfloat16 h1b = __float2bfloat16(v1);
        size_t o = (size_t)n * D + tid;
        out_hi[o] = h0b;
        out_lo[o] = __float2bfloat16(v0 - __bfloat162float(h0b));
        out_hi[o + 256] = h1b;
        out_lo[o + 256] = __float2bfloat16(v1 - __bfloat162float(h1b));
    } else {
        sh_red[tid] = acc0;
        sh_red[tid + 256] = acc1;
        __syncthreads();
        if (tid < C) {
            float s = 0.f;
            for (int h = 0; h < H; h++) s += sh_red[h * C + tid];
            out[(size_t)n * C + tid] = s / (float)H + bias[tid];
        }
    }
}

// ---------------- loss ---------------------------------------------------------
__global__ __launch_bounds__(128)
void loss_kernel(const float* __restrict__ logits,
                 const int* __restrict__ y, const int* __restrict__ mask, int N) {
    __shared__ float red[128];
    int tid = threadIdx.x;
    float lce = 0.f, lw = 0.f;
    int byte_mode = g_mask_byte;
    for (int n = blockIdx.x; n < N; n += gridDim.x) {
        float v = logits[(size_t)n * C2v + tid];
        red[tid] = v;
        __syncthreads();
        #pragma unroll
        for (int o = 64; o; o >>= 1) {
            if (tid < o) red[tid] = fmaxf(red[tid], red[tid + o]);
            __syncthreads();
        }
        float m = red[0];
        __syncthreads();
        red[tid] = expf(v - m);
        __syncthreads();
        #pragma unroll
        for (int o = 64; o; o >>= 1) {
            if (tid < o) red[tid] += red[tid + o];
            __syncthreads();
        }
        if (tid == 0) {
            bool mv = byte_mode ? (((const unsigned char*)mask)[n] != 0) : (mask[n] != 0);
            if (mv) {
                float lse = m + logf(red[0]);
                lce += lse - logits[(size_t)n * C2v + y[n]];
                lw += 1.f;
            }
        }
        __syncthreads();
    }
    if (tid == 0) {
        atomicAdd(&g_accum[0], lce);
        atomicAdd(&g_accum[1], lw);
    }
}

__global__ void finalize_kernel(float* d_out, int write_loss) {
    if (write_loss) d_out[0] = g_accum[0] / g_accum[1];
}

// ---------------- launch --------------------------------------------------------
extern "C" void kernel_launch(void* const* d_in, const int* in_sizes, int n_in,
                              void* d_out, int out_size) {
    const float* x       = (const float*)d_in[0];
    const int*   ei      = (const int*)d_in[1];
    const int*   y       = (const int*)d_in[2];
    const int*   mask    = (const int*)d_in[3];
    const float* W1      = (const float*)d_in[4];
    const float* att_s1  = (const float*)d_in[5];
    const float* att_d1  = (const float*)d_in[6];
    const float* b1      = (const float*)d_in[7];
    const float* W2      = (const float*)d_in[8];
    const float* att_s2  = (const float*)d_in[9];
    const float* att_d2  = (const float*)d_in[10];
    const float* b2      = (const float*)d_in[11];
    float* out_f = (float*)d_out;

    int N = in_sizes[0] / D;        // 20000
    int E = in_sizes[1] / 2;        // 100000
    int EP = E + N;

    float *p_xp, *p_asrc, *p_adst, *p_e;
    __nv_bfloat16 *p_Ahi, *p_Alo, *p_Bhi, *p_Blo;
    cudaGetSymbolAddress((void**)&p_xp, g_xp);
    cudaGetSymbolAddress((void**)&p_asrc, g_asrc);
    cudaGetSymbolAddress((void**)&p_adst, g_adst);
    cudaGetSymbolAddress((void**)&p_e, g_e);
    cudaGetSymbolAddress((void**)&p_Ahi, g_Ahi);
    cudaGetSymbolAddress((void**)&p_Alo, g_Alo);
    cudaGetSymbolAddress((void**)&p_Bhi, g_Bhi);
    cudaGetSymbolAddress((void**)&p_Blo, g_Blo);

    cudaFuncSetAttribute(gemm_mma_kernel,
                         cudaFuncAttributeMaxDynamicSharedMemorySize, GEMM_SMEM);

    int has_loss = (out_size == N * C2v + 1) ? 1 : 0;
    float* p_logits = out_f + has_loss;

    // --- CSR build (shared by both layers) ---
    init_kernel<<<(N + 255) / 256, 256>>>(N);
    hist_kernel<<<(EP + 255) / 256, 256>>>(ei, (const unsigned int*)mask, N / 4, E, N);
    offsets_kernel<<<(N + 255) / 256, 256>>>(N);
    scatter_kernel<<<(EP + 255) / 256, 256>>>(ei, E, N);

    dim3 ggrid(D / 128, (N + 127) / 128);

    // --- layer 1 ---
    split_kernel<<<592, 256>>>(x, p_Ahi, p_Alo, N * D);
    split_kernel<<<256, 256>>>(W1, p_Bhi, p_Blo, D * D);
    gemm_mma_kernel<<<ggrid, 256, GEMM_SMEM>>>(p_Ahi, p_Alo, p_Bhi, p_Blo, p_xp, N);
    att_kernel<<<(N + 7) / 8, 256>>>(p_xp, att_s1, att_d1, p_asrc, p_adst, N, H1v, C1v);
    score_kernel<<<(EP + 255) / 256, 256>>>(p_asrc, p_adst, ei, E, N, H1v);
    // writes bf16 hi/lo directly (GEMM2's A input)
    agg_kernel<<<N, 256>>>(p_xp, p_e, b1, nullptr, p_Ahi, p_Alo, ei, E, H1v, C1v, 0);

    // --- layer 2 ---
    split_kernel<<<256, 256>>>(W2, p_Bhi, p_Blo, D * D);
    gemm_mma_kernel<<<ggrid, 256, GEMM_SMEM>>>(p_Ahi, p_Alo, p_Bhi, p_Blo, p_xp, N);
    att_kernel<<<(N + 7) / 8, 256>>>(p_xp, att_s2, att_d2, p_asrc, p_adst, N, H2v, C2v);
    score_kernel<<<(EP + 255) / 256, 256>>>(p_asrc, p_adst, ei, E, N, H2v);
    agg_kernel<<<N, 256>>>(p_xp, p_e, b2, p_logits, nullptr, nullptr, ei, E, H2v, C2v, 1);

    // --- loss ---
    loss_kernel<<<1024, 128>>>(p_logits, y, mask, N);
    finalize_kernel<<<1, 1>>>(out_f, has_loss);
}

// round 9
// speedup vs baseline: 1.2078x; 1.0587x over previous
#include <cuda_runtime.h>
#include <cuda_bf16.h>
#include <math.h>
#include <stdint.h>

// Problem constants
#define D      512
#define NNODES 20000
#define NEDGES 100000
#define EPRIME (NEDGES + NNODES)
#define H1v    8
#define C1v    64
#define H2v    4
#define C2v    128
#define CHUNK  256

// ---------------- scratch (device globals; no allocation allowed) -------------
__device__ float g_xp[(size_t)NNODES * D];
__device__ float g_asrc[(size_t)NNODES * H1v];
__device__ float g_adst[(size_t)NNODES * H1v];
__device__ float g_e[(size_t)EPRIME * H1v];
__device__ int   g_deg[NNODES];
__device__ int   g_rowstart[NNODES];
__device__ int   g_cursor[NNODES];
__device__ int   g_csr[EPRIME];
__device__ float g_accum[2];
__device__ int   g_mask_byte;
__device__ int   g_total;
__device__ __nv_bfloat16 g_Ahi[(size_t)NNODES * D];
__device__ __nv_bfloat16 g_Alo[(size_t)NNODES * D];
__device__ __nv_bfloat16 g_Bhi[(size_t)D * D];
__device__ __nv_bfloat16 g_Blo[(size_t)D * D];

// ---------------- helpers ----------------------------------------------------
__device__ __forceinline__ float warp_max(float v) {
    #pragma unroll
    for (int o = 16; o; o >>= 1) v = fmaxf(v, __shfl_xor_sync(0xffffffffu, v, o));
    return v;
}
__device__ __forceinline__ float warp_sum(float v) {
    #pragma unroll
    for (int o = 16; o; o >>= 1) v += __shfl_xor_sync(0xffffffffu, v, o);
    return v;
}

__device__ __forceinline__ void mma16816(float* c, const uint32_t* a, const uint32_t* b) {
    asm volatile(
        "mma.sync.aligned.m16n8k16.row.col.f32.bf16.bf16.f32 "
        "{%0,%1,%2,%3}, {%4,%5,%6,%7}, {%8,%9}, {%0,%1,%2,%3};\n"
        : "+f"(c[0]), "+f"(c[1]), "+f"(c[2]), "+f"(c[3])
        : "r"(a[0]), "r"(a[1]), "r"(a[2]), "r"(a[3]), "r"(b[0]), "r"(b[1]));
}
__device__ __forceinline__ void ldsm4(uint32_t* r, uint32_t addr) {
    asm volatile("ldmatrix.sync.aligned.m8n8.x4.shared.b16 {%0,%1,%2,%3}, [%4];\n"
        : "=r"(r[0]), "=r"(r[1]), "=r"(r[2]), "=r"(r[3]) : "r"(addr));
}
__device__ __forceinline__ void ldsm4t(uint32_t* r, uint32_t addr) {
    asm volatile("ldmatrix.sync.aligned.m8n8.x4.trans.shared.b16 {%0,%1,%2,%3}, [%4];\n"
        : "=r"(r[0]), "=r"(r[1]), "=r"(r[2]), "=r"(r[3]) : "r"(addr));
}
__device__ __forceinline__ void cpasync16(uint32_t dst, const void* src, int srcsize) {
    asm volatile("cp.async.cg.shared.global [%0], [%1], 16, %2;\n"
        :: "r"(dst), "l"(src), "r"(srcsize));
}
__device__ __forceinline__ void cp_commit() { asm volatile("cp.async.commit_group;\n"); }
template<int NW> __device__ __forceinline__ void cp_wait() {
    asm volatile("cp.async.wait_group %0;\n" :: "n"(NW));
}

// ---------------- init / CSR build -------------------------------------------
// zeros deg + asrc/adst (layer-1 range N*H1v) + accumulators
__global__ void init_kernel(int N) {
    int i = blockIdx.x * blockDim.x + threadIdx.x;
    if (i < N) g_deg[i] = 0;
    if (i < N * H1v) { g_asrc[i] = 0.f; g_adst[i] = 0.f; }
    if (i == 0) { g_accum[0] = 0.f; g_accum[1] = 0.f; g_total = 0; g_mask_byte = 0; }
}

// zero attention accumulators for layer 2 (runs after layer-1 scores consumed)
__global__ void zero_att_kernel(int n) {
    int i = blockIdx.x * blockDim.x + threadIdx.x;
    if (i < n) { g_asrc[i] = 0.f; g_adst[i] = 0.f; }
}

// histogram of destinations + mask dtype detection (fused)
__global__ void hist_kernel(const int* __restrict__ ei,
                            const unsigned int* __restrict__ m, int nwords,
                            int E, int N) {
    int i = blockIdx.x * blockDim.x + threadIdx.x;
    if (i < nwords) {
        unsigned v = m[i];
        if (v != 0u && v != 1u && v != 0x3F800000u) atomicOr(&g_mask_byte, 1);
    }
    if (i >= E + N) return;
    int d = (i < E) ? ei[E + i] : (i - E);
    atomicAdd(&g_deg[d], 1);
}
__global__ void offsets_kernel(int N) {
    int i = blockIdx.x * blockDim.x + threadIdx.x;
    if (i < N) {
        int base = atomicAdd(&g_total, g_deg[i]);
        g_rowstart[i] = base;
        g_cursor[i] = base;
    }
}
__global__ void scatter_kernel(const int* __restrict__ ei, int E, int N) {
    int i = blockIdx.x * blockDim.x + threadIdx.x;
    if (i >= E + N) return;
    int d = (i < E) ? ei[E + i] : (i - E);
    int pos = atomicAdd(&g_cursor[d], 1);
    g_csr[pos] = i;
}

// ---------------- bf16 hi/lo split ---------------------------------------------
__global__ void split_kernel(const float* __restrict__ x,
                             __nv_bfloat16* __restrict__ hi,
                             __nv_bfloat16* __restrict__ lo, int n) {
    for (int i = blockIdx.x * blockDim.x + threadIdx.x; i < n; i += gridDim.x * blockDim.x) {
        float v = x[i];
        __nv_bfloat16 h = __float2bfloat16(v);
        hi[i] = h;
        lo[i] = __float2bfloat16(v - __bfloat162float(h));
    }
}

// ---------------- tensor-core GEMM + fused attention dot products --------------
// C[M,512] = A[M,512] @ B[512,512]; epilogue computes partial
// asrc[n,h] += sum_c C[n,h*C+c]*att_src[h,c] (atomics), same for adst.
#define LDA_S 40     // 32 + 8 pad (elems)
#define LDB_S 136    // 128 + 8 pad (elems)
#define A_HI_OFF 0
#define A_LO_OFF (128 * LDA_S * 2)                    // 10240
#define B_HI_OFF (A_LO_OFF * 2)                       // 20480
#define B_LO_OFF (B_HI_OFF + 32 * LDB_S * 2)          // 29184
#define STAGE_BYTES (B_LO_OFF + 32 * LDB_S * 2)       // 37888
#define GEMM_SMEM (2 * STAGE_BYTES)                   // 75776

extern __shared__ char smem_raw[];

__global__ __launch_bounds__(256, 2)
void gemm_mma_kernel(const __nv_bfloat16* __restrict__ Ahi,
                     const __nv_bfloat16* __restrict__ Alo,
                     const __nv_bfloat16* __restrict__ Bhi,
                     const __nv_bfloat16* __restrict__ Blo,
                     float* __restrict__ C_out, int M,
                     const float* __restrict__ att_src,
                     const float* __restrict__ att_dst,
                     float* __restrict__ asrc, float* __restrict__ adst,
                     int H, int Ch) {
    const int tid = threadIdx.x;
    const int lane = tid & 31;
    const int wid = tid >> 5;
    const int m0 = blockIdx.y * 128;
    const int n0 = blockIdx.x * 128;
    const int m_base = (wid >> 2) * 64;
    const int n_base = (wid & 3) * 32;

    uint32_t smem_u32 = (uint32_t)__cvta_generic_to_shared(smem_raw);

    const int arow0 = tid >> 2, acol0 = (tid & 3) * 8;
    const int brow0 = tid >> 4, bcol0 = (tid & 15) * 8;

    float acc[4][4][4];
    #pragma unroll
    for (int i = 0; i < 4; i++)
        #pragma unroll
        for (int j = 0; j < 4; j++)
            #pragma unroll
            for (int k = 0; k < 4; k++) acc[i][j][k] = 0.f;

    const int NIT = D / 32;   // 16

    auto load_stage = [&](int it, int s) {
        int k0 = it * 32;
        uint32_t base = smem_u32 + s * STAGE_BYTES;
        #pragma unroll
        for (int c = 0; c < 2; c++) {
            int row = arow0 + c * 64;
            int gr = m0 + row;
            int ok = (gr < M) ? 16 : 0;
            size_t goff = (size_t)gr * D + k0 + acol0;
            uint32_t soff = (uint32_t)(row * LDA_S + acol0) * 2;
            cpasync16(base + A_HI_OFF + soff, Ahi + goff, ok);
            cpasync16(base + A_LO_OFF + soff, Alo + goff, ok);
        }
        #pragma unroll
        for (int c = 0; c < 2; c++) {
            int row = brow0 + c * 16;
            size_t goff = (size_t)(k0 + row) * D + n0 + bcol0;
            uint32_t soff = (uint32_t)(row * LDB_S + bcol0) * 2;
            cpasync16(base + B_HI_OFF + soff, Bhi + goff, 16);
            cpasync16(base + B_LO_OFF + soff, Blo + goff, 16);
        }
        cp_commit();
    };

    load_stage(0, 0);

    for (int it = 0; it < NIT; it++) {
        if (it + 1 < NIT) {
            load_stage(it + 1, (it + 1) & 1);
            cp_wait<1>();
        } else {
            cp_wait<0>();
        }
        __syncthreads();

        uint32_t stg = smem_u32 + (it & 1) * STAGE_BYTES;
        #pragma unroll
        for (int kk = 0; kk < 2; kk++) {
            int kof = kk * 16;
            uint32_t bhi[4][2], blo[4][2];
            #pragma unroll
            for (int p = 0; p < 2; p++) {
                uint32_t off = (uint32_t)((kof + (lane & 7) + 8 * ((lane >> 3) & 1)) * LDB_S
                                          + n_base + p * 16 + 8 * (lane >> 4)) * 2;
                uint32_t r[4];
                ldsm4t(r, stg + B_HI_OFF + off);
                bhi[p * 2][0] = r[0]; bhi[p * 2][1] = r[1];
                bhi[p * 2 + 1][0] = r[2]; bhi[p * 2 + 1][1] = r[3];
                ldsm4t(r, stg + B_LO_OFF + off);
                blo[p * 2][0] = r[0]; blo[p * 2][1] = r[1];
                blo[p * 2 + 1][0] = r[2]; blo[p * 2 + 1][1] = r[3];
            }
            #pragma unroll
            for (int mh = 0; mh < 2; mh++) {
                uint32_t ahi[2][4], alo[2][4];
                #pragma unroll
                for (int q = 0; q < 2; q++) {
                    int mt = mh * 2 + q;
                    uint32_t off = (uint32_t)((m_base + mt * 16 + (lane & 15)) * LDA_S
                                              + kof + 8 * (lane >> 4)) * 2;
                    ldsm4(ahi[q], stg + A_HI_OFF + off);
                    ldsm4(alo[q], stg + A_LO_OFF + off);
                }
                #pragma unroll
                for (int q = 0; q < 2; q++)
                    #pragma unroll
                    for (int nt = 0; nt < 4; nt++) {
                        float* a = acc[mh * 2 + q][nt];
                        mma16816(a, ahi[q], bhi[nt]);
                        mma16816(a, ahi[q], blo[nt]);
                        mma16816(a, alo[q], bhi[nt]);
                    }
            }
        }
        __syncthreads();
    }

    // ---- epilogue: store C ----
    const int gid = lane >> 2, t4 = lane & 3;
    #pragma unroll
    for (int mt = 0; mt < 4; mt++) {
        int r0 = m0 + m_base + mt * 16 + gid;
        int r1 = r0 + 8;
        #pragma unroll
        for (int nt = 0; nt < 4; nt++) {
            int col = n0 + n_base + nt * 8 + t4 * 2;
            if (r0 < M) *(float2*)&C_out[(size_t)r0 * D + col] = make_float2(acc[mt][nt][0], acc[mt][nt][1]);
            if (r1 < M) *(float2*)&C_out[(size_t)r1 * D + col] = make_float2(acc[mt][nt][2], acc[mt][nt][3]);
        }
    }

    // ---- epilogue: fused attention partial dots ----
    // Each thread's 8 columns lie in ONE head (slabs are 32-aligned, heads 64/128-aligned).
    const int h_t = (n0 + n_base) / Ch;
    float av_s[8], av_d[8];
    #pragma unroll
    for (int nt = 0; nt < 4; nt++) {
        int ci = (n0 + n_base + nt * 8 + t4 * 2) % Ch;
        av_s[nt * 2]     = att_src[h_t * Ch + ci];
        av_s[nt * 2 + 1] = att_src[h_t * Ch + ci + 1];
        av_d[nt * 2]     = att_dst[h_t * Ch + ci];
        av_d[nt * 2 + 1] = att_dst[h_t * Ch + ci + 1];
    }
    #pragma unroll
    for (int mt = 0; mt < 4; mt++) {
        float s0 = 0.f, d0 = 0.f, s1 = 0.f, d1 = 0.f;
        #pragma unroll
        for (int nt = 0; nt < 4; nt++) {
            s0 += acc[mt][nt][0] * av_s[nt * 2] + acc[mt][nt][1] * av_s[nt * 2 + 1];
            d0 += acc[mt][nt][0] * av_d[nt * 2] + acc[mt][nt][1] * av_d[nt * 2 + 1];
            s1 += acc[mt][nt][2] * av_s[nt * 2] + acc[mt][nt][3] * av_s[nt * 2 + 1];
            d1 += acc[mt][nt][2] * av_d[nt * 2] + acc[mt][nt][3] * av_d[nt * 2 + 1];
        }
        // reduce across the 4 t4 lanes (lane bits 0-1)
        #pragma unroll
        for (int o = 1; o < 4; o <<= 1) {
            s0 += __shfl_xor_sync(0xffffffffu, s0, o);
            d0 += __shfl_xor_sync(0xffffffffu, d0, o);
            s1 += __shfl_xor_sync(0xffffffffu, s1, o);
            d1 += __shfl_xor_sync(0xffffffffu, d1, o);
        }
        if (t4 == 0) {
            int r0 = m0 + m_base + mt * 16 + gid;
            int r1 = r0 + 8;
            if (r0 < M) {
                atomicAdd(&asrc[r0 * H + h_t], s0);
                atomicAdd(&adst[r0 * H + h_t], d0);
            }
            if (r1 < M) {
                atomicAdd(&asrc[r1 * H + h_t], s1);
                atomicAdd(&adst[r1 * H + h_t], d1);
            }
        }
    }
}

// ---------------- per-edge leaky-relu scores ---------------------------------
__global__ void score_kernel(const float* __restrict__ asrc, const float* __restrict__ adst,
                             const int* __restrict__ ei, int E, int N, int H) {
    int i = blockIdx.x * blockDim.x + threadIdx.x;
    if (i >= E + N) return;
    int s, d;
    if (i < E) { s = ei[i]; d = ei[E + i]; } else { s = d = i - E; }
    for (int h = 0; h < H; h++) {
        float v = asrc[s * H + h] + adst[d * H + h];
        g_e[(size_t)i * H + h] = v > 0.f ? v : 0.2f * v;
    }
}

// ---------------- per-dst softmax + aggregate (block per node) ---------------
// mode 0: elu(agg + bias) -> bf16 hi/lo (direct GEMM2 input)
// mode 1: mean_h(agg) + bias -> fp32 out (logits)
__global__ __launch_bounds__(256)
void agg_kernel(const float* __restrict__ xp, const float* __restrict__ e,
                const float* __restrict__ bias, float* __restrict__ out,
                __nv_bfloat16* __restrict__ out_hi, __nv_bfloat16* __restrict__ out_lo,
                const int* __restrict__ ei, int E, int H, int C, int mode) {
    __shared__ float sh_alpha[CHUNK * H1v];
    __shared__ int   sh_src[CHUNK];
    __shared__ float sh_m[H1v], sh_s[H1v];
    __shared__ float sh_red[512];
    int n = blockIdx.x;
    int tid = threadIdx.x;
    int w = tid >> 5, lane = tid & 31;
    int beg = g_rowstart[n], end = beg + g_deg[n];

    if (w < H) {
        float m = -1e30f;
        for (int i = beg + lane; i < end; i += 32)
            m = fmaxf(m, e[(size_t)g_csr[i] * H + w]);
        m = warp_max(m);
        float s = 0.f;
        for (int i = beg + lane; i < end; i += 32)
            s += expf(e[(size_t)g_csr[i] * H + w] - m);
        s = warp_sum(s);
        if (lane == 0) { sh_m[w] = m; sh_s[w] = s + 1e-16f; }
    }
    __syncthreads();

    int h0 = tid / C, h1 = (tid + 256) / C;
    float acc0 = 0.f, acc1 = 0.f;
    for (int cs = beg; cs < end; cs += CHUNK) {
        int cn = min(CHUNK, end - cs);
        for (int idx = tid; idx < cn; idx += 256) {
            int eid = g_csr[cs + idx];
            sh_src[idx] = (eid < E) ? ei[eid] : (eid - E);
        }
        for (int idx = tid; idx < cn * H; idx += 256) {
            int i = idx / H, h = idx - i * H;
            int eid = g_csr[cs + i];
            sh_alpha[i * H + h] = expf(e[(size_t)eid * H + h] - sh_m[h]) / sh_s[h];
        }
        __syncthreads();
        for (int i = 0; i < cn; i++) {
            const float* row = xp + (size_t)sh_src[i] * D;
            acc0 += sh_alpha[i * H + h0] * row[tid];
            acc1 += sh_alpha[i * H + h1] * row[tid + 256];
        }
        __syncthreads();
    }

    if (mode == 0) {
        float v0 = acc0 + bias[tid];
        float v1 = acc1 + bias[tid + 256];
        v0 = v0 > 0.f ? v0 : expm1f(v0);
        v1 = v1 > 0.f ? v1 : expm1f(v1);
        __nv_bfloat16 h0b = __float2bfloat16(v0);
        __nv_bfloat16 h1b = __float2bfloat16(v1);
        size_t o = (size_t)n * D + tid;
        out_hi[o] = h0b;
        out_lo[o] = __float2bfloat16(v0 - __bfloat162float(h0b));
        out_hi[o + 256] = h1b;
        out_lo[o + 256] = __float2bfloat16(v1 - __bfloat162float(h1b));
    } else {
        sh_red[tid] = acc0;
        sh_red[tid + 256] = acc1;
        __syncthreads();
        if (tid < C) {
            float s = 0.f;
            for (int h = 0; h < H; h++) s += sh_red[h * C + tid];
            out[(size_t)n * C + tid] = s / (float)H + bias[tid];
        }
    }
}

// ---------------- loss (shuffle reductions) -------------------------------------
__global__ __launch_bounds__(128)
void loss_kernel(const float* __restrict__ logits,
                 const int* __restrict__ y, const int* __restrict__ mask, int N) {
    __shared__ float sm[4], ss[4];
    int tid = threadIdx.x;
    int w = tid >> 5, lane = tid & 31;
    float lce = 0.f, lw = 0.f;
    int byte_mode = g_mask_byte;
    for (int n = blockIdx.x; n < N; n += gridDim.x) {
        float v = logits[(size_t)n * C2v + tid];
        float m = warp_max(v);
        if (lane == 0) sm[w] = m;
        __syncthreads();
        m = fmaxf(fmaxf(sm[0], sm[1]), fmaxf(sm[2], sm[3]));
        float s = warp_sum(expf(v - m));
        if (lane == 0) ss[w] = s;
        __syncthreads();
        if (tid == 0) {
            bool mv = byte_mode ? (((const unsigned char*)mask)[n] != 0) : (mask[n] != 0);
            if (mv) {
                float tot = ss[0] + ss[1] + ss[2] + ss[3];
                lce += m + logf(tot) - logits[(size_t)n * C2v + y[n]];
                lw += 1.f;
            }
        }
        __syncthreads();
    }
    if (tid == 0) {
        atomicAdd(&g_accum[0], lce);
        atomicAdd(&g_accum[1], lw);
    }
}

__global__ void finalize_kernel(float* d_out, int write_loss) {
    if (write_loss) d_out[0] = g_accum[0] / g_accum[1];
}

// ---------------- launch --------------------------------------------------------
extern "C" void kernel_launch(void* const* d_in, const int* in_sizes, int n_in,
                              void* d_out, int out_size) {
    const float* x       = (const float*)d_in[0];
    const int*   ei      = (const int*)d_in[1];
    const int*   y       = (const int*)d_in[2];
    const int*   mask    = (const int*)d_in[3];
    const float* W1      = (const float*)d_in[4];
    const float* att_s1  = (const float*)d_in[5];
    const float* att_d1  = (const float*)d_in[6];
    const float* b1      = (const float*)d_in[7];
    const float* W2      = (const float*)d_in[8];
    const float* att_s2  = (const float*)d_in[9];
    const float* att_d2  = (const float*)d_in[10];
    const float* b2      = (const float*)d_in[11];
    float* out_f = (float*)d_out;

    int N = in_sizes[0] / D;        // 20000
    int E = in_sizes[1] / 2;        // 100000
    int EP = E + N;

    float *p_xp, *p_asrc, *p_adst, *p_e;
    __nv_bfloat16 *p_Ahi, *p_Alo, *p_Bhi, *p_Blo;
    cudaGetSymbolAddress((void**)&p_xp, g_xp);
    cudaGetSymbolAddress((void**)&p_asrc, g_asrc);
    cudaGetSymbolAddress((void**)&p_adst, g_adst);
    cudaGetSymbolAddress((void**)&p_e, g_e);
    cudaGetSymbolAddress((void**)&p_Ahi, g_Ahi);
    cudaGetSymbolAddress((void**)&p_Alo, g_Alo);
    cudaGetSymbolAddress((void**)&p_Bhi, g_Bhi);
    cudaGetSymbolAddress((void**)&p_Blo, g_Blo);

    cudaFuncSetAttribute(gemm_mma_kernel,
                         cudaFuncAttributeMaxDynamicSharedMemorySize, GEMM_SMEM);

    int has_loss = (out_size == N * C2v + 1) ? 1 : 0;
    float* p_logits = out_f + has_loss;

    // --- CSR build + zeroing (shared by both layers) ---
    init_kernel<<<(N * H1v + 255) / 256, 256>>>(N);
    hist_kernel<<<(EP + 255) / 256, 256>>>(ei, (const unsigned int*)mask, N / 4, E, N);
    offsets_kernel<<<(N + 255) / 256, 256>>>(N);
    scatter_kernel<<<(EP + 255) / 256, 256>>>(ei, E, N);

    dim3 ggrid(D / 128, (N + 127) / 128);

    // --- layer 1 ---
    split_kernel<<<592, 256>>>(x, p_Ahi, p_Alo, N * D);
    split_kernel<<<256, 256>>>(W1, p_Bhi, p_Blo, D * D);
    gemm_mma_kernel<<<ggrid, 256, GEMM_SMEM>>>(p_Ahi, p_Alo, p_Bhi, p_Blo, p_xp, N,
                                               att_s1, att_d1, p_asrc, p_adst, H1v, C1v);
    score_kernel<<<(EP + 255) / 256, 256>>>(p_asrc, p_adst, ei, E, N, H1v);
    agg_kernel<<<N, 256>>>(p_xp, p_e, b1, nullptr, p_Ahi, p_Alo, ei, E, H1v, C1v, 0);

    // --- layer 2 ---
    zero_att_kernel<<<(N * H2v + 255) / 256, 256>>>(N * H2v);
    split_kernel<<<256, 256>>>(W2, p_Bhi, p_Blo, D * D);
    gemm_mma_kernel<<<ggrid, 256, GEMM_SMEM>>>(p_Ahi, p_Alo, p_Bhi, p_Blo, p_xp, N,
                                               att_s2, att_d2, p_asrc, p_adst, H2v, C2v);
    score_kernel<<<(EP + 255) / 256, 256>>>(p_asrc, p_adst, ei, E, N, H2v);
    agg_kernel<<<N, 256>>>(p_xp, p_e, b2, p_logits, nullptr, nullptr, ei, E, H2v, C2v, 1);

    // --- loss ---
    loss_kernel<<<1024, 128>>>(p_logits, y, mask, N);
    finalize_kernel<<<1, 1>>>(out_f, has_loss);
}

// round 10
// speedup vs baseline: 1.3316x; 1.1025x over previous
#include <cuda_runtime.h>
#include <cuda_bf16.h>
#include <math.h>
#include <stdint.h>

// Problem constants
#define D      512
#define NNODES 20000
#define NEDGES 100000
#define EPRIME (NEDGES + NNODES)
#define H1v    8
#define C1v    64
#define H2v    4
#define C2v    128
#define CHUNK  256

// ---------------- scratch (device globals; no allocation allowed) -------------
__device__ float g_xp[(size_t)NNODES * D];
__device__ float g_asrc[(size_t)NNODES * H1v];
__device__ float g_adst[(size_t)NNODES * H1v];
__device__ int   g_deg[NNODES];
__device__ int   g_rowstart[NNODES];
__device__ int   g_cursor[NNODES];
__device__ int   g_csr[EPRIME];
__device__ float g_accum[2];
__device__ int   g_mask_byte;
__device__ int   g_total;
__device__ __nv_bfloat16 g_Ahi[(size_t)NNODES * D];
__device__ __nv_bfloat16 g_Alo[(size_t)NNODES * D];
__device__ __nv_bfloat16 g_Bhi[(size_t)D * D];
__device__ __nv_bfloat16 g_Blo[(size_t)D * D];
__device__ __nv_bfloat16 g_B2hi[(size_t)D * D];
__device__ __nv_bfloat16 g_B2lo[(size_t)D * D];

// ---------------- helpers ----------------------------------------------------
__device__ __forceinline__ float warp_max(float v) {
    #pragma unroll
    for (int o = 16; o; o >>= 1) v = fmaxf(v, __shfl_xor_sync(0xffffffffu, v, o));
    return v;
}
__device__ __forceinline__ float warp_sum(float v) {
    #pragma unroll
    for (int o = 16; o; o >>= 1) v += __shfl_xor_sync(0xffffffffu, v, o);
    return v;
}

__device__ __forceinline__ void mma16816(float* c, const uint32_t* a, const uint32_t* b) {
    asm volatile(
        "mma.sync.aligned.m16n8k16.row.col.f32.bf16.bf16.f32 "
        "{%0,%1,%2,%3}, {%4,%5,%6,%7}, {%8,%9}, {%0,%1,%2,%3};\n"
        : "+f"(c[0]), "+f"(c[1]), "+f"(c[2]), "+f"(c[3])
        : "r"(a[0]), "r"(a[1]), "r"(a[2]), "r"(a[3]), "r"(b[0]), "r"(b[1]));
}
__device__ __forceinline__ void ldsm4(uint32_t* r, uint32_t addr) {
    asm volatile("ldmatrix.sync.aligned.m8n8.x4.shared.b16 {%0,%1,%2,%3}, [%4];\n"
        : "=r"(r[0]), "=r"(r[1]), "=r"(r[2]), "=r"(r[3]) : "r"(addr));
}
__device__ __forceinline__ void ldsm4t(uint32_t* r, uint32_t addr) {
    asm volatile("ldmatrix.sync.aligned.m8n8.x4.trans.shared.b16 {%0,%1,%2,%3}, [%4];\n"
        : "=r"(r[0]), "=r"(r[1]), "=r"(r[2]), "=r"(r[3]) : "r"(addr));
}
__device__ __forceinline__ void cpasync16(uint32_t dst, const void* src, int srcsize) {
    asm volatile("cp.async.cg.shared.global [%0], [%1], 16, %2;\n"
        :: "r"(dst), "l"(src), "r"(srcsize));
}
__device__ __forceinline__ void cp_commit() { asm volatile("cp.async.commit_group;\n"); }
template<int NW> __device__ __forceinline__ void cp_wait() {
    asm volatile("cp.async.wait_group %0;\n" :: "n"(NW));
}

// ---------------- init / CSR build -------------------------------------------
__global__ void init_kernel(int N) {
    int i = blockIdx.x * blockDim.x + threadIdx.x;
    if (i < N) g_deg[i] = 0;
    if (i < N * H1v) { g_asrc[i] = 0.f; g_adst[i] = 0.f; }
    if (i == 0) { g_accum[0] = 0.f; g_accum[1] = 0.f; g_total = 0; g_mask_byte = 0; }
}
__global__ void zero_att_kernel(int n) {
    int i = blockIdx.x * blockDim.x + threadIdx.x;
    if (i < n) { g_asrc[i] = 0.f; g_adst[i] = 0.f; }
}
__global__ void hist_kernel(const int* __restrict__ ei,
                            const unsigned int* __restrict__ m, int nwords,
                            int E, int N) {
    int i = blockIdx.x * blockDim.x + threadIdx.x;
    if (i < nwords) {
        unsigned v = m[i];
        if (v != 0u && v != 1u && v != 0x3F800000u) atomicOr(&g_mask_byte, 1);
    }
    if (i >= E + N) return;
    int d = (i < E) ? ei[E + i] : (i - E);
    atomicAdd(&g_deg[d], 1);
}
__global__ void offsets_kernel(int N) {
    int i = blockIdx.x * blockDim.x + threadIdx.x;
    if (i < N) {
        int base = atomicAdd(&g_total, g_deg[i]);
        g_rowstart[i] = base;
        g_cursor[i] = base;
    }
}
__global__ void scatter_kernel(const int* __restrict__ ei, int E, int N) {
    int i = blockIdx.x * blockDim.x + threadIdx.x;
    if (i >= E + N) return;
    int d = (i < E) ? ei[E + i] : (i - E);
    int pos = atomicAdd(&g_cursor[d], 1);
    g_csr[pos] = i;
}

// ---------------- bf16 hi/lo split: x, W1, W2 in one launch ---------------------
__device__ __forceinline__ void split_one(float v, __nv_bfloat16* hi, __nv_bfloat16* lo,
                                          size_t idx) {
    __nv_bfloat16 h = __float2bfloat16(v);
    hi[idx] = h;
    lo[idx] = __float2bfloat16(v - __bfloat162float(h));
}
__global__ void split3_kernel(const float* __restrict__ x,
                              const float* __restrict__ W1,
                              const float* __restrict__ W2,
                              __nv_bfloat16* __restrict__ Ahi, __nv_bfloat16* __restrict__ Alo,
                              __nv_bfloat16* __restrict__ B1hi, __nv_bfloat16* __restrict__ B1lo,
                              __nv_bfloat16* __restrict__ B2hi, __nv_bfloat16* __restrict__ B2lo,
                              int nx) {
    const int nw = D * D;
    int total = nx + 2 * nw;
    for (int i = blockIdx.x * blockDim.x + threadIdx.x; i < total; i += gridDim.x * blockDim.x) {
        if (i < nx) split_one(x[i], Ahi, Alo, i);
        else if (i < nx + nw) split_one(W1[i - nx], B1hi, B1lo, i - nx);
        else split_one(W2[i - nx - nw], B2hi, B2lo, i - nx - nw);
    }
}
// split only A (layer-2 hidden) is produced by agg directly; no kernel needed.

// ---------------- tensor-core GEMM + fused attention dot products --------------
#define LDA_S 40
#define LDB_S 136
#define A_HI_OFF 0
#define A_LO_OFF (128 * LDA_S * 2)
#define B_HI_OFF (A_LO_OFF * 2)
#define B_LO_OFF (B_HI_OFF + 32 * LDB_S * 2)
#define STAGE_BYTES (B_LO_OFF + 32 * LDB_S * 2)
#define GEMM_SMEM (2 * STAGE_BYTES)

extern __shared__ char smem_raw[];

__global__ __launch_bounds__(256, 2)
void gemm_mma_kernel(const __nv_bfloat16* __restrict__ Ahi,
                     const __nv_bfloat16* __restrict__ Alo,
                     const __nv_bfloat16* __restrict__ Bhi,
                     const __nv_bfloat16* __restrict__ Blo,
                     float* __restrict__ C_out, int M,
                     const float* __restrict__ att_src,
                     const float* __restrict__ att_dst,
                     float* __restrict__ asrc, float* __restrict__ adst,
                     int H, int Ch) {
    const int tid = threadIdx.x;
    const int lane = tid & 31;
    const int wid = tid >> 5;
    const int m0 = blockIdx.y * 128;
    const int n0 = blockIdx.x * 128;
    const int m_base = (wid >> 2) * 64;
    const int n_base = (wid & 3) * 32;

    uint32_t smem_u32 = (uint32_t)__cvta_generic_to_shared(smem_raw);

    const int arow0 = tid >> 2, acol0 = (tid & 3) * 8;
    const int brow0 = tid >> 4, bcol0 = (tid & 15) * 8;

    float acc[4][4][4];
    #pragma unroll
    for (int i = 0; i < 4; i++)
        #pragma unroll
        for (int j = 0; j < 4; j++)
            #pragma unroll
            for (int k = 0; k < 4; k++) acc[i][j][k] = 0.f;

    const int NIT = D / 32;

    auto load_stage = [&](int it, int s) {
        int k0 = it * 32;
        uint32_t base = smem_u32 + s * STAGE_BYTES;
        #pragma unroll
        for (int c = 0; c < 2; c++) {
            int row = arow0 + c * 64;
            int gr = m0 + row;
            int ok = (gr < M) ? 16 : 0;
            size_t goff = (size_t)gr * D + k0 + acol0;
            uint32_t soff = (uint32_t)(row * LDA_S + acol0) * 2;
            cpasync16(base + A_HI_OFF + soff, Ahi + goff, ok);
            cpasync16(base + A_LO_OFF + soff, Alo + goff, ok);
        }
        #pragma unroll
        for (int c = 0; c < 2; c++) {
            int row = brow0 + c * 16;
            size_t goff = (size_t)(k0 + row) * D + n0 + bcol0;
            uint32_t soff = (uint32_t)(row * LDB_S + bcol0) * 2;
            cpasync16(base + B_HI_OFF + soff, Bhi + goff, 16);
            cpasync16(base + B_LO_OFF + soff, Blo + goff, 16);
        }
        cp_commit();
    };

    load_stage(0, 0);

    for (int it = 0; it < NIT; it++) {
        if (it + 1 < NIT) {
            load_stage(it + 1, (it + 1) & 1);
            cp_wait<1>();
        } else {
            cp_wait<0>();
        }
        __syncthreads();

        uint32_t stg = smem_u32 + (it & 1) * STAGE_BYTES;
        #pragma unroll
        for (int kk = 0; kk < 2; kk++) {
            int kof = kk * 16;
            uint32_t bhi[4][2], blo[4][2];
            #pragma unroll
            for (int p = 0; p < 2; p++) {
                uint32_t off = (uint32_t)((kof + (lane & 7) + 8 * ((lane >> 3) & 1)) * LDB_S
                                          + n_base + p * 16 + 8 * (lane >> 4)) * 2;
                uint32_t r[4];
                ldsm4t(r, stg + B_HI_OFF + off);
                bhi[p * 2][0] = r[0]; bhi[p * 2][1] = r[1];
                bhi[p * 2 + 1][0] = r[2]; bhi[p * 2 + 1][1] = r[3];
                ldsm4t(r, stg + B_LO_OFF + off);
                blo[p * 2][0] = r[0]; blo[p * 2][1] = r[1];
                blo[p * 2 + 1][0] = r[2]; blo[p * 2 + 1][1] = r[3];
            }
            #pragma unroll
            for (int mh = 0; mh < 2; mh++) {
                uint32_t ahi[2][4], alo[2][4];
                #pragma unroll
                for (int q = 0; q < 2; q++) {
                    int mt = mh * 2 + q;
                    uint32_t off = (uint32_t)((m_base + mt * 16 + (lane & 15)) * LDA_S
                                              + kof + 8 * (lane >> 4)) * 2;
                    ldsm4(ahi[q], stg + A_HI_OFF + off);
                    ldsm4(alo[q], stg + A_LO_OFF + off);
                }
                #pragma unroll
                for (int q = 0; q < 2; q++)
                    #pragma unroll
                    for (int nt = 0; nt < 4; nt++) {
                        float* a = acc[mh * 2 + q][nt];
                        mma16816(a, ahi[q], bhi[nt]);
                        mma16816(a, ahi[q], blo[nt]);
                        mma16816(a, alo[q], bhi[nt]);
                    }
            }
        }
        __syncthreads();
    }

    // ---- epilogue: store C ----
    const int gid = lane >> 2, t4 = lane & 3;
    #pragma unroll
    for (int mt = 0; mt < 4; mt++) {
        int r0 = m0 + m_base + mt * 16 + gid;
        int r1 = r0 + 8;
        #pragma unroll
        for (int nt = 0; nt < 4; nt++) {
            int col = n0 + n_base + nt * 8 + t4 * 2;
            if (r0 < M) *(float2*)&C_out[(size_t)r0 * D + col] = make_float2(acc[mt][nt][0], acc[mt][nt][1]);
            if (r1 < M) *(float2*)&C_out[(size_t)r1 * D + col] = make_float2(acc[mt][nt][2], acc[mt][nt][3]);
        }
    }

    // ---- epilogue: fused attention partial dots ----
    const int h_t = (n0 + n_base) / Ch;
    float av_s[8], av_d[8];
    #pragma unroll
    for (int nt = 0; nt < 4; nt++) {
        int ci = (n0 + n_base + nt * 8 + t4 * 2) % Ch;
        av_s[nt * 2]     = att_src[h_t * Ch + ci];
        av_s[nt * 2 + 1] = att_src[h_t * Ch + ci + 1];
        av_d[nt * 2]     = att_dst[h_t * Ch + ci];
        av_d[nt * 2 + 1] = att_dst[h_t * Ch + ci + 1];
    }
    #pragma unroll
    for (int mt = 0; mt < 4; mt++) {
        float s0 = 0.f, d0 = 0.f, s1 = 0.f, d1 = 0.f;
        #pragma unroll
        for (int nt = 0; nt < 4; nt++) {
            s0 += acc[mt][nt][0] * av_s[nt * 2] + acc[mt][nt][1] * av_s[nt * 2 + 1];
            d0 += acc[mt][nt][0] * av_d[nt * 2] + acc[mt][nt][1] * av_d[nt * 2 + 1];
            s1 += acc[mt][nt][2] * av_s[nt * 2] + acc[mt][nt][3] * av_s[nt * 2 + 1];
            d1 += acc[mt][nt][2] * av_d[nt * 2] + acc[mt][nt][3] * av_d[nt * 2 + 1];
        }
        #pragma unroll
        for (int o = 1; o < 4; o <<= 1) {
            s0 += __shfl_xor_sync(0xffffffffu, s0, o);
            d0 += __shfl_xor_sync(0xffffffffu, d0, o);
            s1 += __shfl_xor_sync(0xffffffffu, s1, o);
            d1 += __shfl_xor_sync(0xffffffffu, d1, o);
        }
        if (t4 == 0) {
            int r0 = m0 + m_base + mt * 16 + gid;
            int r1 = r0 + 8;
            if (r0 < M) {
                atomicAdd(&asrc[r0 * H + h_t], s0);
                atomicAdd(&adst[r0 * H + h_t], d0);
            }
            if (r1 < M) {
                atomicAdd(&asrc[r1 * H + h_t], s1);
                atomicAdd(&adst[r1 * H + h_t], d1);
            }
        }
    }
}

// ---------------- fused score + softmax + aggregate (block per node) ------------
// e-values computed on the fly from asrc/adst (leaky-relu).
// mode 0: elu(agg + bias) -> bf16 hi/lo (direct GEMM2 input)
// mode 1: mean_h(agg) + bias -> fp32 out (logits)
__global__ __launch_bounds__(256)
void agg_kernel(const float* __restrict__ xp,
                const float* __restrict__ asrc, const float* __restrict__ adst,
                const float* __restrict__ bias, float* __restrict__ out,
                __nv_bfloat16* __restrict__ out_hi, __nv_bfloat16* __restrict__ out_lo,
                const int* __restrict__ ei, int E, int H, int C, int mode) {
    __shared__ float sh_alpha[CHUNK * H1v];
    __shared__ int   sh_src[CHUNK];
    __shared__ float sh_m[H1v], sh_s[H1v], sh_ad[H1v];
    __shared__ float sh_red[512];
    int n = blockIdx.x;
    int tid = threadIdx.x;
    int w = tid >> 5, lane = tid & 31;
    int beg = g_rowstart[n], end = beg + g_deg[n];

    if (w < H) {
        float ad = adst[n * H + w];
        float m = -1e30f;
        for (int i = beg + lane; i < end; i += 32) {
            int eid = g_csr[i];
            int s = (eid < E) ? ei[eid] : (eid - E);
            float v = asrc[s * H + w] + ad;
            v = v > 0.f ? v : 0.2f * v;
            m = fmaxf(m, v);
        }
        m = warp_max(m);
        float su = 0.f;
        for (int i = beg + lane; i < end; i += 32) {
            int eid = g_csr[i];
            int s = (eid < E) ? ei[eid] : (eid - E);
            float v = asrc[s * H + w] + ad;
            v = v > 0.f ? v : 0.2f * v;
            su += expf(v - m);
        }
        su = warp_sum(su);
        if (lane == 0) { sh_m[w] = m; sh_s[w] = su + 1e-16f; sh_ad[w] = ad; }
    }
    __syncthreads();

    const int hh = tid / (C / 2);     // head for this thread's 2 columns
    float2 acc = make_float2(0.f, 0.f);
    for (int cs = beg; cs < end; cs += CHUNK) {
        int cn = min(CHUNK, end - cs);
        for (int idx = tid; idx < cn; idx += 256) {
            int eid = g_csr[cs + idx];
            sh_src[idx] = (eid < E) ? ei[eid] : (eid - E);
        }
        __syncthreads();
        for (int idx = tid; idx < cn * H; idx += 256) {
            int i = idx / H, h = idx - i * H;
            float v = asrc[sh_src[i] * H + h] + sh_ad[h];
            v = v > 0.f ? v : 0.2f * v;
            sh_alpha[i * H + h] = expf(v - sh_m[h]) / sh_s[h];
        }
        __syncthreads();
        for (int i = 0; i < cn; i++) {
            const float2* row = (const float2*)(xp + (size_t)sh_src[i] * D);
            float2 rv = row[tid];
            float a = sh_alpha[i * H + hh];
            acc.x += a * rv.x;
            acc.y += a * rv.y;
        }
        __syncthreads();
    }

    int c2 = tid * 2;
    if (mode == 0) {
        float v0 = acc.x + bias[c2];
        float v1 = acc.y + bias[c2 + 1];
        v0 = v0 > 0.f ? v0 : expm1f(v0);
        v1 = v1 > 0.f ? v1 : expm1f(v1);
        __nv_bfloat16 h0 = __float2bfloat16(v0);
        __nv_bfloat16 h1 = __float2bfloat16(v1);
        __nv_bfloat162 hp; hp.x = h0; hp.y = h1;
        __nv_bfloat162 lp;
        lp.x = __float2bfloat16(v0 - __bfloat162float(h0));
        lp.y = __float2bfloat16(v1 - __bfloat162float(h1));
        ((__nv_bfloat162*)(out_hi + (size_t)n * D))[tid] = hp;
        ((__nv_bfloat162*)(out_lo + (size_t)n * D))[tid] = lp;
    } else {
        sh_red[c2] = acc.x;
        sh_red[c2 + 1] = acc.y;
        __syncthreads();
        if (tid < C) {
            float s = 0.f;
            for (int h = 0; h < H; h++) s += sh_red[h * C + tid];
            out[(size_t)n * C + tid] = s / (float)H + bias[tid];
        }
    }
}

// ---------------- loss (shuffle reductions) -------------------------------------
__global__ __launch_bounds__(128)
void loss_kernel(const float* __restrict__ logits,
                 const int* __restrict__ y, const int* __restrict__ mask, int N) {
    __shared__ float sm[4], ss[4];
    int tid = threadIdx.x;
    int w = tid >> 5, lane = tid & 31;
    float lce = 0.f, lw = 0.f;
    int byte_mode = g_mask_byte;
    for (int n = blockIdx.x; n < N; n += gridDim.x) {
        float v = logits[(size_t)n * C2v + tid];
        float m = warp_max(v);
        if (lane == 0) sm[w] = m;
        __syncthreads();
        m = fmaxf(fmaxf(sm[0], sm[1]), fmaxf(sm[2], sm[3]));
        float s = warp_sum(expf(v - m));
        if (lane == 0) ss[w] = s;
        __syncthreads();
        if (tid == 0) {
            bool mv = byte_mode ? (((const unsigned char*)mask)[n] != 0) : (mask[n] != 0);
            if (mv) {
                float tot = ss[0] + ss[1] + ss[2] + ss[3];
                lce += m + logf(tot) - logits[(size_t)n * C2v + y[n]];
                lw += 1.f;
            }
        }
        __syncthreads();
    }
    if (tid == 0) {
        atomicAdd(&g_accum[0], lce);
        atomicAdd(&g_accum[1], lw);
    }
}

__global__ void finalize_kernel(float* d_out, int write_loss) {
    if (write_loss) d_out[0] = g_accum[0] / g_accum[1];
}

// ---------------- launch --------------------------------------------------------
extern "C" void kernel_launch(void* const* d_in, const int* in_sizes, int n_in,
                              void* d_out, int out_size) {
    const float* x       = (const float*)d_in[0];
    const int*   ei      = (const int*)d_in[1];
    const int*   y       = (const int*)d_in[2];
    const int*   mask    = (const int*)d_in[3];
    const float* W1      = (const float*)d_in[4];
    const float* att_s1  = (const float*)d_in[5];
    const float* att_d1  = (const float*)d_in[6];
    const float* b1      = (const float*)d_in[7];
    const float* W2      = (const float*)d_in[8];
    const float* att_s2  = (const float*)d_in[9];
    const float* att_d2  = (const float*)d_in[10];
    const float* b2      = (const float*)d_in[11];
    float* out_f = (float*)d_out;

    int N = in_sizes[0] / D;        // 20000
    int E = in_sizes[1] / 2;        // 100000
    int EP = E + N;

    float *p_xp, *p_asrc, *p_adst;
    __nv_bfloat16 *p_Ahi, *p_Alo, *p_Bhi, *p_Blo, *p_B2hi, *p_B2lo;
    cudaGetSymbolAddress((void**)&p_xp, g_xp);
    cudaGetSymbolAddress((void**)&p_asrc, g_asrc);
    cudaGetSymbolAddress((void**)&p_adst, g_adst);
    cudaGetSymbolAddress((void**)&p_Ahi, g_Ahi);
    cudaGetSymbolAddress((void**)&p_Alo, g_Alo);
    cudaGetSymbolAddress((void**)&p_Bhi, g_Bhi);
    cudaGetSymbolAddress((void**)&p_Blo, g_Blo);
    cudaGetSymbolAddress((void**)&p_B2hi, g_B2hi);
    cudaGetSymbolAddress((void**)&p_B2lo, g_B2lo);

    cudaFuncSetAttribute(gemm_mma_kernel,
                         cudaFuncAttributeMaxDynamicSharedMemorySize, GEMM_SMEM);

    int has_loss = (out_size == N * C2v + 1) ? 1 : 0;
    float* p_logits = out_f + has_loss;

    // --- CSR build + zeroing + all splits ---
    init_kernel<<<(N * H1v + 255) / 256, 256>>>(N);
    hist_kernel<<<(EP + 255) / 256, 256>>>(ei, (const unsigned int*)mask, N / 4, E, N);
    offsets_kernel<<<(N + 255) / 256, 256>>>(N);
    scatter_kernel<<<(EP + 255) / 256, 256>>>(ei, E, N);
    split3_kernel<<<1184, 256>>>(x, W1, W2, p_Ahi, p_Alo, p_Bhi, p_Blo,
                                 p_B2hi, p_B2lo, N * D);

    dim3 ggrid(D / 128, (N + 127) / 128);

    // --- layer 1 ---
    gemm_mma_kernel<<<ggrid, 256, GEMM_SMEM>>>(p_Ahi, p_Alo, p_Bhi, p_Blo, p_xp, N,
                                               att_s1, att_d1, p_asrc, p_adst, H1v, C1v);
    agg_kernel<<<N, 256>>>(p_xp, p_asrc, p_adst, b1, nullptr, p_Ahi, p_Alo,
                           ei, E, H1v, C1v, 0);

    // --- layer 2 ---
    zero_att_kernel<<<(N * H2v + 255) / 256, 256>>>(N * H2v);
    gemm_mma_kernel<<<ggrid, 256, GEMM_SMEM>>>(p_Ahi, p_Alo, p_B2hi, p_B2lo, p_xp, N,
                                               att_s2, att_d2, p_asrc, p_adst, H2v, C2v);
    agg_kernel<<<N, 256>>>(p_xp, p_asrc, p_adst, b2, p_logits, nullptr, nullptr,
                           ei, E, H2v, C2v, 1);

    // --- loss ---
    loss_kernel<<<1024, 128>>>(p_logits, y, mask, N);
    finalize_kernel<<<1, 1>>>(out_f, has_loss);
}

// round 11
// speedup vs baseline: 1.5221x; 1.1430x over previous
#include <cuda_runtime.h>
#include <cuda_fp16.h>
#include <math.h>
#include <stdint.h>

// Problem constants
#define D      512
#define NNODES 20000
#define NEDGES 100000
#define EPRIME (NEDGES + NNODES)
#define H1v    8
#define C1v    64
#define H2v    4
#define C2v    128
#define CHUNK  256

// ---------------- scratch (device globals; no allocation allowed) -------------
__device__ float g_xp[(size_t)NNODES * D];
__device__ float g_asrc[(size_t)NNODES * H1v];
__device__ float g_adst[(size_t)NNODES * H1v];
__device__ int   g_deg[NNODES];
__device__ int   g_rowstart[NNODES];
__device__ int   g_cursor[NNODES];
__device__ int   g_csr[EPRIME];
__device__ float g_accum[2];
__device__ int   g_mask_byte;
__device__ int   g_total;
__device__ __half g_Ahi[(size_t)NNODES * D];
__device__ __half g_Alo[(size_t)NNODES * D];
__device__ __half g_Bhi[(size_t)D * D];
__device__ __half g_B2hi[(size_t)D * D];

// ---------------- helpers ----------------------------------------------------
__device__ __forceinline__ float warp_max(float v) {
    #pragma unroll
    for (int o = 16; o; o >>= 1) v = fmaxf(v, __shfl_xor_sync(0xffffffffu, v, o));
    return v;
}
__device__ __forceinline__ float warp_sum(float v) {
    #pragma unroll
    for (int o = 16; o; o >>= 1) v += __shfl_xor_sync(0xffffffffu, v, o);
    return v;
}

__device__ __forceinline__ void mma16816(float* c, const uint32_t* a, const uint32_t* b) {
    asm volatile(
        "mma.sync.aligned.m16n8k16.row.col.f32.f16.f16.f32 "
        "{%0,%1,%2,%3}, {%4,%5,%6,%7}, {%8,%9}, {%0,%1,%2,%3};\n"
        : "+f"(c[0]), "+f"(c[1]), "+f"(c[2]), "+f"(c[3])
        : "r"(a[0]), "r"(a[1]), "r"(a[2]), "r"(a[3]), "r"(b[0]), "r"(b[1]));
}
__device__ __forceinline__ void ldsm4(uint32_t* r, uint32_t addr) {
    asm volatile("ldmatrix.sync.aligned.m8n8.x4.shared.b16 {%0,%1,%2,%3}, [%4];\n"
        : "=r"(r[0]), "=r"(r[1]), "=r"(r[2]), "=r"(r[3]) : "r"(addr));
}
__device__ __forceinline__ void ldsm4t(uint32_t* r, uint32_t addr) {
    asm volatile("ldmatrix.sync.aligned.m8n8.x4.trans.shared.b16 {%0,%1,%2,%3}, [%4];\n"
        : "=r"(r[0]), "=r"(r[1]), "=r"(r[2]), "=r"(r[3]) : "r"(addr));
}
__device__ __forceinline__ void cpasync16(uint32_t dst, const void* src, int srcsize) {
    asm volatile("cp.async.cg.shared.global [%0], [%1], 16, %2;\n"
        :: "r"(dst), "l"(src), "r"(srcsize));
}
__device__ __forceinline__ void cp_commit() { asm volatile("cp.async.commit_group;\n"); }
template<int NW> __device__ __forceinline__ void cp_wait() {
    asm volatile("cp.async.wait_group %0;\n" :: "n"(NW));
}

// ---------------- init / CSR build -------------------------------------------
__global__ void init_kernel(int N) {
    int i = blockIdx.x * blockDim.x + threadIdx.x;
    if (i < N) g_deg[i] = 0;
    if (i == 0) { g_accum[0] = 0.f; g_accum[1] = 0.f; g_total = 0; g_mask_byte = 0; }
}
__global__ void hist_kernel(const int* __restrict__ ei,
                            const unsigned int* __restrict__ m, int nwords,
                            int E, int N) {
    int i = blockIdx.x * blockDim.x + threadIdx.x;
    if (i < nwords) {
        unsigned v = m[i];
        if (v != 0u && v != 1u && v != 0x3F800000u) atomicOr(&g_mask_byte, 1);
    }
    if (i >= E + N) return;
    int d = (i < E) ? ei[E + i] : (i - E);
    atomicAdd(&g_deg[d], 1);
}
__global__ void offsets_kernel(int N) {
    int i = blockIdx.x * blockDim.x + threadIdx.x;
    if (i < N) {
        int base = atomicAdd(&g_total, g_deg[i]);
        g_rowstart[i] = base;
        g_cursor[i] = base;
    }
}
__global__ void scatter_kernel(const int* __restrict__ ei, int E, int N) {
    int i = blockIdx.x * blockDim.x + threadIdx.x;
    if (i >= E + N) return;
    int d = (i < E) ? ei[E + i] : (i - E);
    int pos = atomicAdd(&g_cursor[d], 1);
    g_csr[pos] = i;
}

// ---------------- fp16 splits: A hi/lo; W1, W2 hi only --------------------------
__global__ void split3_kernel(const float* __restrict__ x,
                              const float* __restrict__ W1,
                              const float* __restrict__ W2,
                              __half* __restrict__ Ahi, __half* __restrict__ Alo,
                              __half* __restrict__ B1hi, __half* __restrict__ B2hi,
                              int nx) {
    const int nw = D * D;
    int total = nx + 2 * nw;
    for (int i = blockIdx.x * blockDim.x + threadIdx.x; i < total; i += gridDim.x * blockDim.x) {
        if (i < nx) {
            float v = x[i];
            __half h = __float2half_rn(v);
            Ahi[i] = h;
            Alo[i] = __float2half_rn(v - __half2float(h));
        } else if (i < nx + nw) {
            B1hi[i - nx] = __float2half_rn(W1[i - nx]);
        } else {
            B2hi[i - nx - nw] = __float2half_rn(W2[i - nx - nw]);
        }
    }
}

// ---------------- tensor-core GEMM + fused attention (atomic-free) -------------
// C[M,512] = A@B with A=ahi+alo fp16 pair, B=bhi fp16. 2 mma products.
// Epilogue: per-(row,head) att dots reduced via smem, plain stores.
#define LDA_S 40
#define LDB_S 136
#define A_HI_OFF 0
#define A_LO_OFF (128 * LDA_S * 2)                    // 10240
#define B_HI_OFF (A_LO_OFF * 2)                       // 20480
#define STAGE_BYTES (B_HI_OFF + 32 * LDB_S * 2 - A_LO_OFF)  // 10240+8704=18944? (see below)
#undef STAGE_BYTES
#define STAGE_BYTES (A_LO_OFF * 2 + 32 * LDB_S * 2)   // 20480 + 8704 = 29184
#define GEMM_SMEM (2 * STAGE_BYTES)                   // 58368

extern __shared__ char smem_raw[];

__global__ __launch_bounds__(256, 2)
void gemm_mma_kernel(const __half* __restrict__ Ahi,
                     const __half* __restrict__ Alo,
                     const __half* __restrict__ Bhi,
                     float* __restrict__ C_out, int M,
                     const float* __restrict__ att_src,
                     const float* __restrict__ att_dst,
                     float* __restrict__ asrc, float* __restrict__ adst,
                     int H, int Ch) {
    const int tid = threadIdx.x;
    const int lane = tid & 31;
    const int wid = tid >> 5;
    const int m0 = blockIdx.y * 128;
    const int n0 = blockIdx.x * 128;
    const int m_base = (wid >> 2) * 64;
    const int warp_n = wid & 3;
    const int n_base = warp_n * 32;

    uint32_t smem_u32 = (uint32_t)__cvta_generic_to_shared(smem_raw);

    const int arow0 = tid >> 2, acol0 = (tid & 3) * 8;
    const int brow0 = tid >> 4, bcol0 = (tid & 15) * 8;

    float acc[4][4][4];
    #pragma unroll
    for (int i = 0; i < 4; i++)
        #pragma unroll
        for (int j = 0; j < 4; j++)
            #pragma unroll
            for (int k = 0; k < 4; k++) acc[i][j][k] = 0.f;

    const int NIT = D / 32;

    auto load_stage = [&](int it, int s) {
        int k0 = it * 32;
        uint32_t base = smem_u32 + s * STAGE_BYTES;
        #pragma unroll
        for (int c = 0; c < 2; c++) {
            int row = arow0 + c * 64;
            int gr = m0 + row;
            int ok = (gr < M) ? 16 : 0;
            size_t goff = (size_t)gr * D + k0 + acol0;
            uint32_t soff = (uint32_t)(row * LDA_S + acol0) * 2;
            cpasync16(base + A_HI_OFF + soff, Ahi + goff, ok);
            cpasync16(base + A_LO_OFF + soff, Alo + goff, ok);
        }
        #pragma unroll
        for (int c = 0; c < 2; c++) {
            int row = brow0 + c * 16;
            size_t goff = (size_t)(k0 + row) * D + n0 + bcol0;
            uint32_t soff = (uint32_t)(row * LDB_S + bcol0) * 2;
            cpasync16(base + B_HI_OFF + soff, Bhi + goff, 16);
        }
        cp_commit();
    };

    load_stage(0, 0);

    for (int it = 0; it < NIT; it++) {
        if (it + 1 < NIT) {
            load_stage(it + 1, (it + 1) & 1);
            cp_wait<1>();
        } else {
            cp_wait<0>();
        }
        __syncthreads();

        uint32_t stg = smem_u32 + (it & 1) * STAGE_BYTES;
        #pragma unroll
        for (int kk = 0; kk < 2; kk++) {
            int kof = kk * 16;
            uint32_t bhi[4][2];
            #pragma unroll
            for (int p = 0; p < 2; p++) {
                uint32_t off = (uint32_t)((kof + (lane & 7) + 8 * ((lane >> 3) & 1)) * LDB_S
                                          + n_base + p * 16 + 8 * (lane >> 4)) * 2;
                uint32_t r[4];
                ldsm4t(r, stg + B_HI_OFF + off);
                bhi[p * 2][0] = r[0]; bhi[p * 2][1] = r[1];
                bhi[p * 2 + 1][0] = r[2]; bhi[p * 2 + 1][1] = r[3];
            }
            #pragma unroll
            for (int mh = 0; mh < 2; mh++) {
                uint32_t ahi[2][4], alo[2][4];
                #pragma unroll
                for (int q = 0; q < 2; q++) {
                    int mt = mh * 2 + q;
                    uint32_t off = (uint32_t)((m_base + mt * 16 + (lane & 15)) * LDA_S
                                              + kof + 8 * (lane >> 4)) * 2;
                    ldsm4(ahi[q], stg + A_HI_OFF + off);
                    ldsm4(alo[q], stg + A_LO_OFF + off);
                }
                #pragma unroll
                for (int q = 0; q < 2; q++)
                    #pragma unroll
                    for (int nt = 0; nt < 4; nt++) {
                        float* a = acc[mh * 2 + q][nt];
                        mma16816(a, ahi[q], bhi[nt]);
                        mma16816(a, alo[q], bhi[nt]);
                    }
            }
        }
        __syncthreads();
    }

    // ---- epilogue: store C ----
    const int gid = lane >> 2, t4 = lane & 3;
    #pragma unroll
    for (int mt = 0; mt < 4; mt++) {
        int r0 = m0 + m_base + mt * 16 + gid;
        int r1 = r0 + 8;
        #pragma unroll
        for (int nt = 0; nt < 4; nt++) {
            int col = n0 + n_base + nt * 8 + t4 * 2;
            if (r0 < M) *(float2*)&C_out[(size_t)r0 * D + col] = make_float2(acc[mt][nt][0], acc[mt][nt][1]);
            if (r1 < M) *(float2*)&C_out[(size_t)r1 * D + col] = make_float2(acc[mt][nt][2], acc[mt][nt][3]);
        }
    }

    // ---- epilogue: attention dots, smem cross-warp reduce, plain stores ----
    // Each warp's 32 cols lie in one head; heads are fully covered by this block.
    const int h_t = (n0 + n_base) / Ch;       // global head of this warp
    float av_s[8], av_d[8];
    #pragma unroll
    for (int nt = 0; nt < 4; nt++) {
        int ci = (n0 + n_base + nt * 8 + t4 * 2) % Ch;
        av_s[nt * 2]     = att_src[h_t * Ch + ci];
        av_s[nt * 2 + 1] = att_src[h_t * Ch + ci + 1];
        av_d[nt * 2]     = att_dst[h_t * Ch + ci];
        av_d[nt * 2 + 1] = att_dst[h_t * Ch + ci + 1];
    }
    float* s_arr = (float*)smem_raw;          // [4][128]
    float* d_arr = s_arr + 512;               // [4][128]
    #pragma unroll
    for (int mt = 0; mt < 4; mt++) {
        float s0 = 0.f, d0 = 0.f, s1 = 0.f, d1 = 0.f;
        #pragma unroll
        for (int nt = 0; nt < 4; nt++) {
            s0 += acc[mt][nt][0] * av_s[nt * 2] + acc[mt][nt][1] * av_s[nt * 2 + 1];
            d0 += acc[mt][nt][0] * av_d[nt * 2] + acc[mt][nt][1] * av_d[nt * 2 + 1];
            s1 += acc[mt][nt][2] * av_s[nt * 2] + acc[mt][nt][3] * av_s[nt * 2 + 1];
            d1 += acc[mt][nt][2] * av_d[nt * 2] + acc[mt][nt][3] * av_d[nt * 2 + 1];
        }
        #pragma unroll
        for (int o = 1; o < 4; o <<= 1) {
            s0 += __shfl_xor_sync(0xffffffffu, s0, o);
            d0 += __shfl_xor_sync(0xffffffffu, d0, o);
            s1 += __shfl_xor_sync(0xffffffffu, s1, o);
            d1 += __shfl_xor_sync(0xffffffffu, d1, o);
        }
        if (t4 == 0) {
            int rl0 = m_base + mt * 16 + gid;     // local rows 0..127
            int rl1 = rl0 + 8;
            s_arr[warp_n * 128 + rl0] = s0;
            d_arr[warp_n * 128 + rl0] = d0;
            s_arr[warp_n * 128 + rl1] = s1;
            d_arr[warp_n * 128 + rl1] = d1;
        }
    }
    __syncthreads();
    const int nh = 128 / Ch;                  // heads per block (2 or 1)
    const int wph = Ch / 32;                  // warps per head (2 or 4)
    if (tid < 128 * nh) {
        int row = tid & 127;
        int hl = tid >> 7;
        float ssum = 0.f, dsum = 0.f;
        for (int w = hl * wph; w < hl * wph + wph; w++) {
            ssum += s_arr[w * 128 + row];
            dsum += d_arr[w * 128 + row];
        }
        int gr = m0 + row;
        if (gr < M) {
            int gh = n0 / Ch + hl;
            asrc[gr * H + gh] = ssum;
            adst[gr * H + gh] = dsum;
        }
    }
}

// ---------------- fused score + softmax + aggregate (block per node) ------------
__global__ __launch_bounds__(256)
void agg_kernel(const float* __restrict__ xp,
                const float* __restrict__ asrc, const float* __restrict__ adst,
                const float* __restrict__ bias, float* __restrict__ out,
                __half* __restrict__ out_hi, __half* __restrict__ out_lo,
                const int* __restrict__ ei, int E, int H, int C, int mode) {
    __shared__ float sh_alpha[CHUNK * H1v];
    __shared__ int   sh_src[CHUNK];
    __shared__ float sh_m[H1v], sh_s[H1v], sh_ad[H1v];
    __shared__ float sh_red[512];
    int n = blockIdx.x;
    int tid = threadIdx.x;
    int w = tid >> 5, lane = tid & 31;
    int beg = g_rowstart[n], end = beg + g_deg[n];

    if (w < H) {
        float ad = adst[n * H + w];
        float m = -1e30f;
        for (int i = beg + lane; i < end; i += 32) {
            int eid = g_csr[i];
            int s = (eid < E) ? ei[eid] : (eid - E);
            float v = asrc[s * H + w] + ad;
            v = v > 0.f ? v : 0.2f * v;
            m = fmaxf(m, v);
        }
        m = warp_max(m);
        float su = 0.f;
        for (int i = beg + lane; i < end; i += 32) {
            int eid = g_csr[i];
            int s = (eid < E) ? ei[eid] : (eid - E);
            float v = asrc[s * H + w] + ad;
            v = v > 0.f ? v : 0.2f * v;
            su += expf(v - m);
        }
        su = warp_sum(su);
        if (lane == 0) { sh_m[w] = m; sh_s[w] = su + 1e-16f; sh_ad[w] = ad; }
    }
    __syncthreads();

    const int hh = tid / (C / 2);
    float2 acc = make_float2(0.f, 0.f);
    for (int cs = beg; cs < end; cs += CHUNK) {
        int cn = min(CHUNK, end - cs);
        for (int idx = tid; idx < cn; idx += 256) {
            int eid = g_csr[cs + idx];
            sh_src[idx] = (eid < E) ? ei[eid] : (eid - E);
        }
        __syncthreads();
        for (int idx = tid; idx < cn * H; idx += 256) {
            int i = idx / H, h = idx - i * H;
            float v = asrc[sh_src[i] * H + h] + sh_ad[h];
            v = v > 0.f ? v : 0.2f * v;
            sh_alpha[i * H + h] = expf(v - sh_m[h]) / sh_s[h];
        }
        __syncthreads();
        for (int i = 0; i < cn; i++) {
            const float2* row = (const float2*)(xp + (size_t)sh_src[i] * D);
            float2 rv = row[tid];
            float a = sh_alpha[i * H + hh];
            acc.x += a * rv.x;
            acc.y += a * rv.y;
        }
        __syncthreads();
    }

    int c2 = tid * 2;
    if (mode == 0) {
        float v0 = acc.x + bias[c2];
        float v1 = acc.y + bias[c2 + 1];
        v0 = v0 > 0.f ? v0 : expm1f(v0);
        v1 = v1 > 0.f ? v1 : expm1f(v1);
        __half h0 = __float2half_rn(v0);
        __half h1 = __float2half_rn(v1);
        __half2 hp; hp.x = h0; hp.y = h1;
        __half2 lp;
        lp.x = __float2half_rn(v0 - __half2float(h0));
        lp.y = __float2half_rn(v1 - __half2float(h1));
        ((__half2*)(out_hi + (size_t)n * D))[tid] = hp;
        ((__half2*)(out_lo + (size_t)n * D))[tid] = lp;
    } else {
        sh_red[c2] = acc.x;
        sh_red[c2 + 1] = acc.y;
        __syncthreads();
        if (tid < C) {
            float s = 0.f;
            for (int h = 0; h < H; h++) s += sh_red[h * C + tid];
            out[(size_t)n * C + tid] = s / (float)H + bias[tid];
        }
    }
}

// ---------------- loss (shuffle reductions) -------------------------------------
__global__ __launch_bounds__(128)
void loss_kernel(const float* __restrict__ logits,
                 const int* __restrict__ y, const int* __restrict__ mask, int N) {
    __shared__ float sm[4], ss[4];
    int tid = threadIdx.x;
    int w = tid >> 5, lane = tid & 31;
    float lce = 0.f, lw = 0.f;
    int byte_mode = g_mask_byte;
    for (int n = blockIdx.x; n < N; n += gridDim.x) {
        float v = logits[(size_t)n * C2v + tid];
        float m = warp_max(v);
        if (lane == 0) sm[w] = m;
        __syncthreads();
        m = fmaxf(fmaxf(sm[0], sm[1]), fmaxf(sm[2], sm[3]));
        float s = warp_sum(expf(v - m));
        if (lane == 0) ss[w] = s;
        __syncthreads();
        if (tid == 0) {
            bool mv = byte_mode ? (((const unsigned char*)mask)[n] != 0) : (mask[n] != 0);
            if (mv) {
                float tot = ss[0] + ss[1] + ss[2] + ss[3];
                lce += m + logf(tot) - logits[(size_t)n * C2v + y[n]];
                lw += 1.f;
            }
        }
        __syncthreads();
    }
    if (tid == 0) {
        atomicAdd(&g_accum[0], lce);
        atomicAdd(&g_accum[1], lw);
    }
}

__global__ void finalize_kernel(float* d_out, int write_loss) {
    if (write_loss) d_out[0] = g_accum[0] / g_accum[1];
}

// ---------------- launch --------------------------------------------------------
extern "C" void kernel_launch(void* const* d_in, const int* in_sizes, int n_in,
                              void* d_out, int out_size) {
    const float* x       = (const float*)d_in[0];
    const int*   ei      = (const int*)d_in[1];
    const int*   y       = (const int*)d_in[2];
    const int*   mask    = (const int*)d_in[3];
    const float* W1      = (const float*)d_in[4];
    const float* att_s1  = (const float*)d_in[5];
    const float* att_d1  = (const float*)d_in[6];
    const float* b1      = (const float*)d_in[7];
    const float* W2      = (const float*)d_in[8];
    const float* att_s2  = (const float*)d_in[9];
    const float* att_d2  = (const float*)d_in[10];
    const float* b2      = (const float*)d_in[11];
    float* out_f = (float*)d_out;

    int N = in_sizes[0] / D;        // 20000
    int E = in_sizes[1] / 2;        // 100000
    int EP = E + N;

    float *p_xp, *p_asrc, *p_adst;
    __half *p_Ahi, *p_Alo, *p_Bhi, *p_B2hi;
    cudaGetSymbolAddress((void**)&p_xp, g_xp);
    cudaGetSymbolAddress((void**)&p_asrc, g_asrc);
    cudaGetSymbolAddress((void**)&p_adst, g_adst);
    cudaGetSymbolAddress((void**)&p_Ahi, g_Ahi);
    cudaGetSymbolAddress((void**)&p_Alo, g_Alo);
    cudaGetSymbolAddress((void**)&p_Bhi, g_Bhi);
    cudaGetSymbolAddress((void**)&p_B2hi, g_B2hi);

    cudaFuncSetAttribute(gemm_mma_kernel,
                         cudaFuncAttributeMaxDynamicSharedMemorySize, GEMM_SMEM);

    int has_loss = (out_size == N * C2v + 1) ? 1 : 0;
    float* p_logits = out_f + has_loss;

    // --- CSR build + splits ---
    init_kernel<<<(N + 255) / 256, 256>>>(N);
    hist_kernel<<<(EP + 255) / 256, 256>>>(ei, (const unsigned int*)mask, N / 4, E, N);
    offsets_kernel<<<(N + 255) / 256, 256>>>(N);
    scatter_kernel<<<(EP + 255) / 256, 256>>>(ei, E, N);
    split3_kernel<<<1184, 256>>>(x, W1, W2, p_Ahi, p_Alo, p_Bhi, p_B2hi, N * D);

    dim3 ggrid(D / 128, (N + 127) / 128);

    // --- layer 1 ---
    gemm_mma_kernel<<<ggrid, 256, GEMM_SMEM>>>(p_Ahi, p_Alo, p_Bhi, p_xp, N,
                                               att_s1, att_d1, p_asrc, p_adst, H1v, C1v);
    agg_kernel<<<N, 256>>>(p_xp, p_asrc, p_adst, b1, nullptr, p_Ahi, p_Alo,
                           ei, E, H1v, C1v, 0);

    // --- layer 2 ---
    gemm_mma_kernel<<<ggrid, 256, GEMM_SMEM>>>(p_Ahi, p_Alo, p_B2hi, p_xp, N,
                                               att_s2, att_d2, p_asrc, p_adst, H2v, C2v);
    agg_kernel<<<N, 256>>>(p_xp, p_asrc, p_adst, b2, p_logits, nullptr, nullptr,
                           ei, E, H2v, C2v, 1);

    // --- loss ---
    loss_kernel<<<1024, 128>>>(p_logits, y, mask, N);
    finalize_kernel<<<1, 1>>>(out_f, has_loss);
}

// round 12
// speedup vs baseline: 1.7967x; 1.1804x over previous
#include <cuda_runtime.h>
#include <cuda_fp16.h>
#include <math.h>
#include <stdint.h>

// Problem constants
#define D      512
#define NNODES 20000
#define NEDGES 100000
#define EPRIME (NEDGES + NNODES)
#define H1v    8
#define C1v    64
#define H2v    4
#define C2v    128
#define CHUNK  128

// ---------------- scratch (device globals; no allocation allowed) -------------
__device__ float g_xp[(size_t)NNODES * D];
__device__ float g_asrc[(size_t)NNODES * H1v];
__device__ float g_adst[(size_t)NNODES * H1v];
__device__ int   g_deg[NNODES];
__device__ int   g_rowstart[NNODES];
__device__ int   g_cursor[NNODES];
__device__ int   g_csr[EPRIME];
__device__ float g_accum[2];
__device__ int   g_mask_byte;
__device__ int   g_total;
__device__ __half g_Ahi[(size_t)NNODES * D];
__device__ __half g_Alo[(size_t)NNODES * D];
__device__ __half g_Bhi[(size_t)D * D];
__device__ __half g_B2hi[(size_t)D * D];

// ---------------- helpers ----------------------------------------------------
__device__ __forceinline__ float warp_max(float v) {
    #pragma unroll
    for (int o = 16; o; o >>= 1) v = fmaxf(v, __shfl_xor_sync(0xffffffffu, v, o));
    return v;
}
__device__ __forceinline__ float warp_sum(float v) {
    #pragma unroll
    for (int o = 16; o; o >>= 1) v += __shfl_xor_sync(0xffffffffu, v, o);
    return v;
}

__device__ __forceinline__ void mma16816(float* c, const uint32_t* a, const uint32_t* b) {
    asm volatile(
        "mma.sync.aligned.m16n8k16.row.col.f32.f16.f16.f32 "
        "{%0,%1,%2,%3}, {%4,%5,%6,%7}, {%8,%9}, {%0,%1,%2,%3};\n"
        : "+f"(c[0]), "+f"(c[1]), "+f"(c[2]), "+f"(c[3])
        : "r"(a[0]), "r"(a[1]), "r"(a[2]), "r"(a[3]), "r"(b[0]), "r"(b[1]));
}
__device__ __forceinline__ void ldsm4(uint32_t* r, uint32_t addr) {
    asm volatile("ldmatrix.sync.aligned.m8n8.x4.shared.b16 {%0,%1,%2,%3}, [%4];\n"
        : "=r"(r[0]), "=r"(r[1]), "=r"(r[2]), "=r"(r[3]) : "r"(addr));
}
__device__ __forceinline__ void ldsm4t(uint32_t* r, uint32_t addr) {
    asm volatile("ldmatrix.sync.aligned.m8n8.x4.trans.shared.b16 {%0,%1,%2,%3}, [%4];\n"
        : "=r"(r[0]), "=r"(r[1]), "=r"(r[2]), "=r"(r[3]) : "r"(addr));
}
__device__ __forceinline__ void cpasync16(uint32_t dst, const void* src, int srcsize) {
    asm volatile("cp.async.cg.shared.global [%0], [%1], 16, %2;\n"
        :: "r"(dst), "l"(src), "r"(srcsize));
}
__device__ __forceinline__ void cp_commit() { asm volatile("cp.async.commit_group;\n"); }
template<int NW> __device__ __forceinline__ void cp_wait() {
    asm volatile("cp.async.wait_group %0;\n" :: "n"(NW));
}

// ---------------- CSR build -----------------------------------------------------
__global__ void hist_kernel(const int* __restrict__ ei,
                            const unsigned int* __restrict__ m, int nwords,
                            int E, int N) {
    int i = blockIdx.x * blockDim.x + threadIdx.x;
    if (i < nwords) {
        unsigned v = m[i];
        if (v != 0u && v != 1u && v != 0x3F800000u) atomicOr(&g_mask_byte, 1);
    }
    if (i >= E + N) return;
    int d = (i < E) ? ei[E + i] : (i - E);
    atomicAdd(&g_deg[d], 1);
}
__global__ void offsets_kernel(int N) {
    int i = blockIdx.x * blockDim.x + threadIdx.x;
    if (i < N) {
        int base = atomicAdd(&g_total, g_deg[i]);
        g_rowstart[i] = base;
        g_cursor[i] = base;
    }
}
__global__ void scatter_kernel(const int* __restrict__ ei, int E, int N) {
    int i = blockIdx.x * blockDim.x + threadIdx.x;
    if (i >= E + N) return;
    int d = (i < E) ? ei[E + i] : (i - E);
    int pos = atomicAdd(&g_cursor[d], 1);
    g_csr[pos] = i;
}

// ---------------- fp16 splits + init (fused) ------------------------------------
__global__ void split3_kernel(const float* __restrict__ x,
                              const float* __restrict__ W1,
                              const float* __restrict__ W2,
                              __half* __restrict__ Ahi, __half* __restrict__ Alo,
                              __half* __restrict__ B1hi, __half* __restrict__ B2hi,
                              int nx, int N) {
    const int nw = D * D;
    int total = nx + 2 * nw;
    int gi = blockIdx.x * blockDim.x + threadIdx.x;
    if (gi < N) g_deg[gi] = 0;
    if (gi == 0) { g_accum[0] = 0.f; g_accum[1] = 0.f; g_total = 0; g_mask_byte = 0; }
    for (int i = gi; i < total; i += gridDim.x * blockDim.x) {
        if (i < nx) {
            float v = x[i];
            __half h = __float2half_rn(v);
            Ahi[i] = h;
            Alo[i] = __float2half_rn(v - __half2float(h));
        } else if (i < nx + nw) {
            B1hi[i - nx] = __float2half_rn(W1[i - nx]);
        } else {
            B2hi[i - nx - nw] = __float2half_rn(W2[i - nx - nw]);
        }
    }
}

// ---------------- tensor-core GEMM + fused attention (atomic-free) --------------
#define LDA_S 40
#define LDB_S 136
#define A_HI_OFF 0
#define A_LO_OFF (128 * LDA_S * 2)                    // 10240
#define B_HI_OFF (A_LO_OFF * 2)                       // 20480
#define STAGE_BYTES (A_LO_OFF * 2 + 32 * LDB_S * 2)   // 29184
#define GEMM_SMEM (2 * STAGE_BYTES)                   // 58368

extern __shared__ char smem_raw[];

__global__ __launch_bounds__(256, 2)
void gemm_mma_kernel(const __half* __restrict__ Ahi,
                     const __half* __restrict__ Alo,
                     const __half* __restrict__ Bhi,
                     float* __restrict__ C_out, int M,
                     const float* __restrict__ att_src,
                     const float* __restrict__ att_dst,
                     float* __restrict__ asrc, float* __restrict__ adst,
                     int H, int Ch) {
    const int tid = threadIdx.x;
    const int lane = tid & 31;
    const int wid = tid >> 5;
    const int m0 = blockIdx.y * 128;
    const int n0 = blockIdx.x * 128;
    const int m_base = (wid >> 2) * 64;
    const int warp_n = wid & 3;
    const int n_base = warp_n * 32;

    uint32_t smem_u32 = (uint32_t)__cvta_generic_to_shared(smem_raw);

    const int arow0 = tid >> 2, acol0 = (tid & 3) * 8;
    const int brow0 = tid >> 4, bcol0 = (tid & 15) * 8;

    float acc[4][4][4];
    #pragma unroll
    for (int i = 0; i < 4; i++)
        #pragma unroll
        for (int j = 0; j < 4; j++)
            #pragma unroll
            for (int k = 0; k < 4; k++) acc[i][j][k] = 0.f;

    const int NIT = D / 32;

    auto load_stage = [&](int it, int s) {
        int k0 = it * 32;
        uint32_t base = smem_u32 + s * STAGE_BYTES;
        #pragma unroll
        for (int c = 0; c < 2; c++) {
            int row = arow0 + c * 64;
            int gr = m0 + row;
            int ok = (gr < M) ? 16 : 0;
            size_t goff = (size_t)gr * D + k0 + acol0;
            uint32_t soff = (uint32_t)(row * LDA_S + acol0) * 2;
            cpasync16(base + A_HI_OFF + soff, Ahi + goff, ok);
            cpasync16(base + A_LO_OFF + soff, Alo + goff, ok);
        }
        #pragma unroll
        for (int c = 0; c < 2; c++) {
            int row = brow0 + c * 16;
            size_t goff = (size_t)(k0 + row) * D + n0 + bcol0;
            uint32_t soff = (uint32_t)(row * LDB_S + bcol0) * 2;
            cpasync16(base + B_HI_OFF + soff, Bhi + goff, 16);
        }
        cp_commit();
    };

    load_stage(0, 0);

    for (int it = 0; it < NIT; it++) {
        if (it + 1 < NIT) {
            load_stage(it + 1, (it + 1) & 1);
            cp_wait<1>();
        } else {
            cp_wait<0>();
        }
        __syncthreads();

        uint32_t stg = smem_u32 + (it & 1) * STAGE_BYTES;
        #pragma unroll
        for (int kk = 0; kk < 2; kk++) {
            int kof = kk * 16;
            uint32_t bhi[4][2];
            #pragma unroll
            for (int p = 0; p < 2; p++) {
                uint32_t off = (uint32_t)((kof + (lane & 7) + 8 * ((lane >> 3) & 1)) * LDB_S
                                          + n_base + p * 16 + 8 * (lane >> 4)) * 2;
                uint32_t r[4];
                ldsm4t(r, stg + B_HI_OFF + off);
                bhi[p * 2][0] = r[0]; bhi[p * 2][1] = r[1];
                bhi[p * 2 + 1][0] = r[2]; bhi[p * 2 + 1][1] = r[3];
            }
            #pragma unroll
            for (int mh = 0; mh < 2; mh++) {
                uint32_t ahi[2][4], alo[2][4];
                #pragma unroll
                for (int q = 0; q < 2; q++) {
                    int mt = mh * 2 + q;
                    uint32_t off = (uint32_t)((m_base + mt * 16 + (lane & 15)) * LDA_S
                                              + kof + 8 * (lane >> 4)) * 2;
                    ldsm4(ahi[q], stg + A_HI_OFF + off);
                    ldsm4(alo[q], stg + A_LO_OFF + off);
                }
                #pragma unroll
                for (int q = 0; q < 2; q++)
                    #pragma unroll
                    for (int nt = 0; nt < 4; nt++) {
                        float* a = acc[mh * 2 + q][nt];
                        mma16816(a, ahi[q], bhi[nt]);
                        mma16816(a, alo[q], bhi[nt]);
                    }
            }
        }
        __syncthreads();
    }

    // ---- epilogue: store C ----
    const int gid = lane >> 2, t4 = lane & 3;
    #pragma unroll
    for (int mt = 0; mt < 4; mt++) {
        int r0 = m0 + m_base + mt * 16 + gid;
        int r1 = r0 + 8;
        #pragma unroll
        for (int nt = 0; nt < 4; nt++) {
            int col = n0 + n_base + nt * 8 + t4 * 2;
            if (r0 < M) *(float2*)&C_out[(size_t)r0 * D + col] = make_float2(acc[mt][nt][0], acc[mt][nt][1]);
            if (r1 < M) *(float2*)&C_out[(size_t)r1 * D + col] = make_float2(acc[mt][nt][2], acc[mt][nt][3]);
        }
    }

    // ---- epilogue: attention dots, smem cross-warp reduce, plain stores ----
    const int h_t = (n0 + n_base) / Ch;
    float av_s[8], av_d[8];
    #pragma unroll
    for (int nt = 0; nt < 4; nt++) {
        int ci = (n0 + n_base + nt * 8 + t4 * 2) % Ch;
        av_s[nt * 2]     = att_src[h_t * Ch + ci];
        av_s[nt * 2 + 1] = att_src[h_t * Ch + ci + 1];
        av_d[nt * 2]     = att_dst[h_t * Ch + ci];
        av_d[nt * 2 + 1] = att_dst[h_t * Ch + ci + 1];
    }
    float* s_arr = (float*)smem_raw;
    float* d_arr = s_arr + 512;
    #pragma unroll
    for (int mt = 0; mt < 4; mt++) {
        float s0 = 0.f, d0 = 0.f, s1 = 0.f, d1 = 0.f;
        #pragma unroll
        for (int nt = 0; nt < 4; nt++) {
            s0 += acc[mt][nt][0] * av_s[nt * 2] + acc[mt][nt][1] * av_s[nt * 2 + 1];
            d0 += acc[mt][nt][0] * av_d[nt * 2] + acc[mt][nt][1] * av_d[nt * 2 + 1];
            s1 += acc[mt][nt][2] * av_s[nt * 2] + acc[mt][nt][3] * av_s[nt * 2 + 1];
            d1 += acc[mt][nt][2] * av_d[nt * 2] + acc[mt][nt][3] * av_d[nt * 2 + 1];
        }
        #pragma unroll
        for (int o = 1; o < 4; o <<= 1) {
            s0 += __shfl_xor_sync(0xffffffffu, s0, o);
            d0 += __shfl_xor_sync(0xffffffffu, d0, o);
            s1 += __shfl_xor_sync(0xffffffffu, s1, o);
            d1 += __shfl_xor_sync(0xffffffffu, d1, o);
        }
        if (t4 == 0) {
            int rl0 = m_base + mt * 16 + gid;
            int rl1 = rl0 + 8;
            s_arr[warp_n * 128 + rl0] = s0;
            d_arr[warp_n * 128 + rl0] = d0;
            s_arr[warp_n * 128 + rl1] = s1;
            d_arr[warp_n * 128 + rl1] = d1;
        }
    }
    __syncthreads();
    const int nh = 128 / Ch;
    const int wph = Ch / 32;
    if (tid < 128 * nh) {
        int row = tid & 127;
        int hl = tid >> 7;
        float ssum = 0.f, dsum = 0.f;
        for (int w = hl * wph; w < hl * wph + wph; w++) {
            ssum += s_arr[w * 128 + row];
            dsum += d_arr[w * 128 + row];
        }
        int gr = m0 + row;
        if (gr < M) {
            int gh = n0 / Ch + hl;
            asrc[gr * H + gh] = ssum;
            adst[gr * H + gh] = dsum;
        }
    }
}

// ---------------- fused score+softmax+aggregate (+CE loss in mode 1) ------------
// 128 threads/block, 4 columns per thread -> 2x blocks/SM vs 256.
__global__ __launch_bounds__(128)
void agg_kernel(const float* __restrict__ xp,
                const float* __restrict__ asrc, const float* __restrict__ adst,
                const float* __restrict__ bias, float* __restrict__ out,
                __half* __restrict__ out_hi, __half* __restrict__ out_lo,
                const int* __restrict__ ei,
                const int* __restrict__ y, const int* __restrict__ mask,
                int E, int H, int lgH, int C, int mode) {
    __shared__ float sh_alpha[CHUNK * H1v];
    __shared__ int   sh_src[CHUNK];
    __shared__ float sh_m[H1v], sh_s[H1v], sh_ad[H1v];
    __shared__ float sh_red[512];
    __shared__ float sm4[4], ss4[4];
    int n = blockIdx.x;
    int tid = threadIdx.x;
    int w = tid >> 5, lane = tid & 31;
    int beg = g_rowstart[n], end = beg + g_deg[n];

    // softmax stats: 4 warps cover H heads
    for (int h = w; h < H; h += 4) {
        float ad = adst[n * H + h];
        float m = -1e30f;
        for (int i = beg + lane; i < end; i += 32) {
            int eid = g_csr[i];
            int s = (eid < E) ? ei[eid] : (eid - E);
            float v = asrc[s * H + h] + ad;
            v = v > 0.f ? v : 0.2f * v;
            m = fmaxf(m, v);
        }
        m = warp_max(m);
        float su = 0.f;
        for (int i = beg + lane; i < end; i += 32) {
            int eid = g_csr[i];
            int s = (eid < E) ? ei[eid] : (eid - E);
            float v = asrc[s * H + h] + ad;
            v = v > 0.f ? v : 0.2f * v;
            su += expf(v - m);
        }
        su = warp_sum(su);
        if (lane == 0) { sh_m[h] = m; sh_s[h] = su + 1e-16f; sh_ad[h] = ad; }
    }
    __syncthreads();

    const int p1 = tid + 128;                 // second float2-pair index
    const int hh0 = tid / (C / 2);
    const int hh1 = p1 / (C / 2);
    float2 acc0 = make_float2(0.f, 0.f), acc1 = make_float2(0.f, 0.f);
    for (int cs = beg; cs < end; cs += CHUNK) {
        int cn = min(CHUNK, end - cs);
        if (tid < cn) {
            int eid = g_csr[cs + tid];
            sh_src[tid] = (eid < E) ? ei[eid] : (eid - E);
        }
        __syncthreads();
        for (int idx = tid; idx < (cn << lgH); idx += 128) {
            int i = idx >> lgH, h = idx & (H - 1);
            float v = asrc[sh_src[i] * H + h] + sh_ad[h];
            v = v > 0.f ? v : 0.2f * v;
            sh_alpha[(i << lgH) + h] = expf(v - sh_m[h]) / sh_s[h];
        }
        __syncthreads();
        for (int i = 0; i < cn; i++) {
            const float2* row = (const float2*)(xp + (size_t)sh_src[i] * D);
            float a0 = sh_alpha[(i << lgH) + hh0];
            float a1 = sh_alpha[(i << lgH) + hh1];
            float2 r0 = row[tid], r1 = row[p1];
            acc0.x += a0 * r0.x; acc0.y += a0 * r0.y;
            acc1.x += a1 * r1.x; acc1.y += a1 * r1.y;
        }
        __syncthreads();
    }

    if (mode == 0) {
        float v0 = acc0.x + bias[tid * 2];
        float v1 = acc0.y + bias[tid * 2 + 1];
        float v2 = acc1.x + bias[p1 * 2];
        float v3 = acc1.y + bias[p1 * 2 + 1];
        v0 = v0 > 0.f ? v0 : expm1f(v0);
        v1 = v1 > 0.f ? v1 : expm1f(v1);
        v2 = v2 > 0.f ? v2 : expm1f(v2);
        v3 = v3 > 0.f ? v3 : expm1f(v3);
        __half h0 = __float2half_rn(v0), h1 = __float2half_rn(v1);
        __half h2 = __float2half_rn(v2), h3 = __float2half_rn(v3);
        __half2 hp0; hp0.x = h0; hp0.y = h1;
        __half2 hp1; hp1.x = h2; hp1.y = h3;
        __half2 lp0, lp1;
        lp0.x = __float2half_rn(v0 - __half2float(h0));
        lp0.y = __float2half_rn(v1 - __half2float(h1));
        lp1.x = __float2half_rn(v2 - __half2float(h2));
        lp1.y = __float2half_rn(v3 - __half2float(h3));
        __half2* oh = (__half2*)(out_hi + (size_t)n * D);
        __half2* ol = (__half2*)(out_lo + (size_t)n * D);
        oh[tid] = hp0; oh[p1] = hp1;
        ol[tid] = lp0; ol[p1] = lp1;
    } else {
        sh_red[tid * 2]     = acc0.x;
        sh_red[tid * 2 + 1] = acc0.y;
        sh_red[p1 * 2]      = acc1.x;
        sh_red[p1 * 2 + 1]  = acc1.y;
        __syncthreads();
        // C == 128: every thread owns one class column
        float s = 0.f;
        for (int h = 0; h < H; h++) s += sh_red[h * C + tid];
        float logit = s / (float)H + bias[tid];
        out[(size_t)n * C + tid] = logit;
        __syncthreads();
        sh_red[tid] = logit;                   // stash for label lookup
        float mx = warp_max(logit);
        if (lane == 0) sm4[w] = mx;
        __syncthreads();
        mx = fmaxf(fmaxf(sm4[0], sm4[1]), fmaxf(sm4[2], sm4[3]));
        float se = warp_sum(expf(logit - mx));
        if (lane == 0) ss4[w] = se;
        __syncthreads();
        if (tid == 0) {
            bool mv = g_mask_byte ? (((const unsigned char*)mask)[n] != 0) : (mask[n] != 0);
            if (mv) {
                float lse = mx + logf(ss4[0] + ss4[1] + ss4[2] + ss4[3]);
                atomicAdd(&g_accum[0], lse - sh_red[y[n]]);
                atomicAdd(&g_accum[1], 1.f);
            }
        }
    }
}

__global__ void finalize_kernel(float* d_out, int write_loss) {
    if (write_loss) d_out[0] = g_accum[0] / g_accum[1];
}

// ---------------- launch --------------------------------------------------------
extern "C" void kernel_launch(void* const* d_in, const int* in_sizes, int n_in,
                              void* d_out, int out_size) {
    const float* x       = (const float*)d_in[0];
    const int*   ei      = (const int*)d_in[1];
    const int*   y       = (const int*)d_in[2];
    const int*   mask    = (const int*)d_in[3];
    const float* W1      = (const float*)d_in[4];
    const float* att_s1  = (const float*)d_in[5];
    const float* att_d1  = (const float*)d_in[6];
    const float* b1      = (const float*)d_in[7];
    const float* W2      = (const float*)d_in[8];
    const float* att_s2  = (const float*)d_in[9];
    const float* att_d2  = (const float*)d_in[10];
    const float* b2      = (const float*)d_in[11];
    float* out_f = (float*)d_out;

    int N = in_sizes[0] / D;        // 20000
    int E = in_sizes[1] / 2;        // 100000
    int EP = E + N;

    float *p_xp, *p_asrc, *p_adst;
    __half *p_Ahi, *p_Alo, *p_Bhi, *p_B2hi;
    cudaGetSymbolAddress((void**)&p_xp, g_xp);
    cudaGetSymbolAddress((void**)&p_asrc, g_asrc);
    cudaGetSymbolAddress((void**)&p_adst, g_adst);
    cudaGetSymbolAddress((void**)&p_Ahi, g_Ahi);
    cudaGetSymbolAddress((void**)&p_Alo, g_Alo);
    cudaGetSymbolAddress((void**)&p_Bhi, g_Bhi);
    cudaGetSymbolAddress((void**)&p_B2hi, g_B2hi);

    cudaFuncSetAttribute(gemm_mma_kernel,
                         cudaFuncAttributeMaxDynamicSharedMemorySize, GEMM_SMEM);

    int has_loss = (out_size == N * C2v + 1) ? 1 : 0;
    float* p_logits = out_f + has_loss;

    // --- splits + init (fused), then CSR chain ---
    split3_kernel<<<1184, 256>>>(x, W1, W2, p_Ahi, p_Alo, p_Bhi, p_B2hi, N * D, N);
    hist_kernel<<<(EP + 255) / 256, 256>>>(ei, (const unsigned int*)mask, N / 4, E, N);
    offsets_kernel<<<(N + 255) / 256, 256>>>(N);
    scatter_kernel<<<(EP + 255) / 256, 256>>>(ei, E, N);

    dim3 ggrid(D / 128, (N + 127) / 128);

    // --- layer 1 ---
    gemm_mma_kernel<<<ggrid, 256, GEMM_SMEM>>>(p_Ahi, p_Alo, p_Bhi, p_xp, N,
                                               att_s1, att_d1, p_asrc, p_adst, H1v, C1v);
    agg_kernel<<<N, 128>>>(p_xp, p_asrc, p_adst, b1, nullptr, p_Ahi, p_Alo,
                           ei, nullptr, nullptr, E, H1v, 3, C1v, 0);

    // --- layer 2 (agg fuses CE loss) ---
    gemm_mma_kernel<<<ggrid, 256, GEMM_SMEM>>>(p_Ahi, p_Alo, p_B2hi, p_xp, N,
                                               att_s2, att_d2, p_asrc, p_adst, H2v, C2v);
    agg_kernel<<<N, 128>>>(p_xp, p_asrc, p_adst, b2, p_logits, nullptr, nullptr,
                           ei, y, mask, E, H2v, 2, C2v, 1);

    finalize_kernel<<<1, 1>>>(out_f, has_loss);
}